// round 13
// baseline (speedup 1.0000x reference)
#include <cuda_runtime.h>
#include <cuda_fp16.h>
#include <mma.h>
#include <math.h>
#include <stdint.h>

using namespace nvcuda;

#define NTOK   2112
#define BATCH  2
#define HD     1024
#define NHEADS 8
#define HDIM   128
#define LAYERS 8
#define ROWS   (BATCH*NTOK)          // 4224
#define NZ     (BATCH*NHEADS)        // 16
#define SZZ    ((long long)NTOK*NTOK)

// ------------------------- fp32 scratch --------------------------------------
__device__ float g_c1re[BATCH*16*64*33];
__device__ float g_c1im[BATCH*16*64*33];
__device__ float g_tok [BATCH*NTOK*32];
__device__ float g_t   [ROWS*HD];
__device__ float g_buf1[ROWS*HD];
__device__ float g_bhd [2*16384];            // combined head biases

// ------------------------- fp16 scratch --------------------------------------
__device__ __half g_qkv16[ROWS*3*HD];
__device__ __half g_b1hi [ROWS*HD],        g_b1lo [ROWS*HD];
__device__ __half g_qhi  [NZ*NTOK*HDIM];
__device__ __half g_khi  [NZ*NTOK*HDIM];
__device__ __half g_vthi [NZ*HDIM*NTOK];
__device__ __half g_shi  [NZ*NTOK*NTOK];
__device__ __half g_aohi [ROWS*HD],        g_aolo [ROWS*HD];
__device__ __half g_hidhi[ROWS*4*HD],      g_hidlo[ROWS*4*HD];
__device__ __half g_tshi [ROWS*HD];
// weights (single fp16)
__device__ __half g_wqkvhi[LAYERS*3*HD*HD];
__device__ __half g_wprhi [LAYERS*HD*HD];
__device__ __half g_wf1hi [LAYERS*4*HD*HD];
__device__ __half g_wf2hi [LAYERS*4*HD*HD];
__device__ __half g_whd   [2LL*16384*512];   // combined mag+phase head weights

__device__ __forceinline__ float geluf(float v) {
    return 0.5f * v * (1.0f + erff(v * 0.7071067811865476f));
}
__device__ __forceinline__ uint32_t smem_u32(const void* p) {
    uint32_t a;
    asm("{ .reg .u64 t; cvta.to.shared.u64 t, %1; cvt.u32.u64 %0, t; }"
        : "=r"(a) : "l"(p));
    return a;
}
__device__ __forceinline__ void cp16(void* dst, const void* src, int srcBytes) {
    asm volatile("cp.async.cg.shared.global [%0], [%1], 16, %2;"
                 :: "r"(smem_u32(dst)), "l"(src), "r"(srcBytes) : "memory");
}
#define CP_COMMIT() asm volatile("cp.async.commit_group;" ::: "memory")
#define CP_WAIT1()  asm volatile("cp.async.wait_group 1;" ::: "memory")
#define CP_WAIT0()  asm volatile("cp.async.wait_group 0;" ::: "memory")

// ============================ wmma split-fp16 GEMM ===========================
// C = act(alpha * A B^T + bias) [+R]  (NT layout).
// PROD: 3 = AhBh+AhBl+AlBh; 2 = AhBh+AlBh (B single); 1 = AhBh (both single).
// OSPLIT: 0 = fp32 C; 1 = split fp16 Ch+Cl; 2 = single fp16 Ch.
// SCATTER: heads layout; z-batched via sCb (out) and sCh2 (bias stride).
// CAUSAL epilogue writes 0 above the diagonal (softmax tail pre-zeroed).
#define MG_SMEM 81920

template<int BIAS, int GELU, int RES, int SCATTER, int CAUSAL, int TRIK,
         int OSPLIT, int PROD>
__global__ __launch_bounds__(256, 2)
void k_mgemm(const __half* __restrict__ Ah_, const __half* __restrict__ Al_,
             long long lda,
             const __half* __restrict__ Bh_, const __half* __restrict__ Bl_,
             long long ldb,
             const float* __restrict__ bias, const float* __restrict__ Rres,
             float* __restrict__ C, __half* __restrict__ Ch,
             __half* __restrict__ Cl, long long ldc,
             int M, int N, int K, float alpha,
             int H, long long sAb, long long sAh2, long long sBb, long long sBh2,
             long long sCb, long long sCh2)
{
    if (CAUSAL && blockIdx.x > blockIdx.y) return;
    int m0 = blockIdx.y*128, n0 = blockIdx.x*128;
    int z = blockIdx.z; int bz = z / H, hz = z - bz*H;
    long long aoff = bz*sAb + hz*sAh2 + (long long)m0*lda;
    long long boff = bz*sBb + hz*sBh2 + (long long)n0*ldb;
    long long coff = bz*sCb + hz*sCh2;
    Ah_ += aoff; Al_ += aoff; Bh_ += boff; Bl_ += boff;
    if (SCATTER) {
        C += bz*sCb;
        if (BIAS) bias += bz*sCh2;
    } else {
        C += coff; if (OSPLIT) { Ch += coff; if (OSPLIT==1) Cl += coff; }
    }

    extern __shared__ char dsm[];
    __half* sbuf  = (__half*)dsm;            // 2 x 20480 halfs (K-loop)
    float*  stage = (float*)dsm;             // 128x128 fp32 (epilogue, aliases)

    int tid = threadIdx.x, wid = tid >> 5;
    int wm = wid & 3, wn = wid >> 2;
    int row2 = tid >> 2, seg = tid & 3;

    int mrows = M - m0; if (mrows > 128) mrows = 128;
    int nrows = N - n0; if (nrows > 128) nrows = 128;
    int Kend = TRIK ? (m0 + 128 < K ? m0 + 128 : K) : K;
    int nch = Kend >> 5;

    wmma::fragment<wmma::accumulator, 16, 16, 16, float> c[2][4];
#pragma unroll
    for (int i = 0; i < 2; i++)
#pragma unroll
        for (int j = 0; j < 4; j++) wmma::fill_fragment(c[i][j], 0.0f);

    const __half* srcs[4] = {Ah_, Al_, Bh_, Bl_};
    long long lds[2] = {lda, ldb};

    auto prefetch = [&](int chunk, int s) {
        long long k0 = (long long)chunk << 5;
        __half* base = sbuf + s*20480;
#pragma unroll
        for (int tno = 0; tno < 4; tno++) {
            if (PROD == 1 && (tno == 1 || tno == 3)) continue;
            if (PROD == 2 && tno == 3) continue;
            int lim = (tno>>1) ? nrows : mrows;
#pragma unroll
            for (int i = 0; i < 2; i++) {
                int r = row2 + 64*i;
                int v2 = (r < lim) ? 16 : 0;
                cp16(base + tno*5120 + r*40 + seg*8,
                     srcs[tno] + (long long)r*lds[tno>>1] + k0 + seg*8, v2);
            }
        }
    };

    prefetch(0, 0);
    CP_COMMIT();

    for (int i = 0; i < nch; i++) {
        if (i + 1 < nch) { prefetch(i+1, (i+1)&1); CP_COMMIT(); CP_WAIT1(); }
        else             { CP_WAIT0(); }
        __syncthreads();
        __half* b = sbuf + (i&1)*20480;
        __half* As_h = b;
        __half* As_l = b + 5120;
        __half* Bs_h = b + 10240;
        __half* Bs_l = b + 15360;
#pragma unroll
        for (int kk = 0; kk < 32; kk += 16) {
            wmma::fragment<wmma::matrix_a, 16, 16, 16, __half, wmma::row_major> fah[2], fal[2];
#pragma unroll
            for (int ii = 0; ii < 2; ii++) {
                wmma::load_matrix_sync(fah[ii], As_h + (wm*32 + ii*16)*40 + kk, 40);
                if (PROD >= 2)
                    wmma::load_matrix_sync(fal[ii], As_l + (wm*32 + ii*16)*40 + kk, 40);
            }
#pragma unroll
            for (int j = 0; j < 4; j++) {
                wmma::fragment<wmma::matrix_b, 16, 16, 16, __half, wmma::col_major> fb;
                wmma::load_matrix_sync(fb, Bs_h + (wn*64 + j*16)*40 + kk, 40);
                wmma::mma_sync(c[0][j], fah[0], fb, c[0][j]);
                wmma::mma_sync(c[1][j], fah[1], fb, c[1][j]);
                if (PROD >= 2) {
                    wmma::mma_sync(c[0][j], fal[0], fb, c[0][j]);
                    wmma::mma_sync(c[1][j], fal[1], fb, c[1][j]);
                }
                if (PROD == 3) {
                    wmma::load_matrix_sync(fb, Bs_l + (wn*64 + j*16)*40 + kk, 40);
                    wmma::mma_sync(c[0][j], fah[0], fb, c[0][j]);
                    wmma::mma_sync(c[1][j], fah[1], fb, c[1][j]);
                }
            }
        }
        __syncthreads();
    }

    // ---- single-pass epilogue: all fragments -> 128x128 fp32 stage ----
#pragma unroll
    for (int ii = 0; ii < 2; ii++)
#pragma unroll
        for (int j = 0; j < 4; j++) {
            if (SCATTER)
                wmma::store_matrix_sync(stage + (wn*64 + j*16)*128 + (wm*32 + ii*16),
                                        c[ii][j], 128, wmma::mem_col_major);
            else
                wmma::store_matrix_sync(stage + (wm*32 + ii*16)*128 + wn*64 + j*16,
                                        c[ii][j], 128, wmma::mem_row_major);
        }
    __syncthreads();
    for (int e = tid; e < 16384; e += 256) {
        int r, col;
        float v;
        if (SCATTER) { r = e & 127; col = e >> 7; v = stage[col*128 + r]; }
        else         { r = e >> 7;  col = e & 127; v = stage[e]; }
        int gm = m0 + r, gn = n0 + col;
        if (gm >= M || gn >= N) continue;
        v *= alpha;
        if (BIAS) v += bias[gn];
        if (GELU) v = geluf(v);
        if (CAUSAL && gn > gm) v = 0.f;   // pre-zero masked region for softmax/SV
        if (SCATTER) {
            int b2 = gm / NTOK;
            int nt = gm - b2*NTOK;
            long long o = ((long long)b2*16384 + (long long)(gn & 15)*1024
                           + (gn >> 4)) * NTOK + nt;
            C[o] = v;
        } else {
            long long o = (long long)gm*ldc + gn;
            if (RES) v += Rres[o];
            if (OSPLIT == 1) {
                __half hh = __float2half(v);
                Ch[o] = hh;
                Cl[o] = __float2half(v - __half2float(hh));
            } else if (OSPLIT == 2) {
                Ch[o] = __float2half(v);
            } else C[o] = v;
        }
    }
}

// ============================ elementwise kernels ============================

// hi-only fp16 convert
__global__ void k_split1(const float* __restrict__ src,
                         __half* __restrict__ hi, long long n) {
    long long i = ((long long)blockIdx.x*256 + threadIdx.x) * 4;
    if (i + 4 <= n) {
        float4 v = *(const float4*)(src + i);
        *(__half2*)(hi + i)     = __halves2half2(__float2half(v.x), __float2half(v.y));
        *(__half2*)(hi + i + 2) = __halves2half2(__float2half(v.z), __float2half(v.w));
    } else {
        for (; i < n; i++) hi[i] = __float2half(src[i]);
    }
}

// fused rope + qkv reorganize; reads fp16 qkv, writes q/k/v single fp16
__global__ void k_rope_split() {
    int row = blockIdx.x;
    int b = row / NTOK, t = row - b*NTOK;
    const __half* base = g_qkv16 + (long long)row*3*HD;
    int tid = threadIdx.x;
    for (int idx = tid; idx < 512; idx += 256) {
        int h = idx >> 6, i = idx & 63;
        float div = expf((float)i * -0.14391156831212787f);
        float ang = (float)t * div;
        float s, c; sincosf(ang, &s, &c);
        int z = b*NHEADS + h;
        long long qi = ((long long)z*NTOK + t)*HDIM + i;
        {
            float q1 = __half2float(base[h*HDIM + i]);
            float q2 = __half2float(base[h*HDIM + i + 64]);
            g_qhi[qi]    = __float2half(q1 + q1*c - q2*s);
            g_qhi[qi+64] = __float2half(q2 + q2*c + q1*s);
        }
        {
            float k1 = __half2float(base[HD + h*HDIM + i]);
            float k2 = __half2float(base[HD + h*HDIM + i + 64]);
            g_khi[qi]    = __float2half(k1 + k1*c - k2*s);
            g_khi[qi+64] = __float2half(k2 + k2*c + k1*s);
        }
    }
    for (int idx = tid; idx < 1024; idx += 256) {
        int h = idx >> 7, d = idx & 127;
        int z = b*NHEADS + h;
        long long vi = ((long long)z*HDIM + d)*NTOK + t;
        g_vthi[vi] = base[2*HD + h*HDIM + d];
    }
}

__global__ void k_dft1(const float* __restrict__ x) {
    int idx = blockIdx.x * 256 + threadIdx.x;
    if (idx >= BATCH*16*64*33) return;
    int v  = idx % 33;
    int t  = idx / 33;
    int y  = t % 64;
    int bc = t / 64;
    const float* xr = x + ((long long)bc*64 + y)*64;
    float re = 0.f, im = 0.f;
    for (int j = 0; j < 64; j++) {
        int m = (v*j) & 63;
        float ang = -0.09817477042468103f * (float)m;
        float s, c; sincosf(ang, &s, &c);
        float xv = xr[j];
        re += xv * c;
        im += xv * s;
    }
    g_c1re[idx] = re;
    g_c1im[idx] = im;
}

__global__ void k_dft2() {
    int idx = blockIdx.x * 256 + threadIdx.x;
    if (idx >= BATCH*16*64*33) return;
    int v  = idx % 33;
    int t  = idx / 33;
    int r  = t % 64;
    int bc = t / 64;
    int b  = bc / 16, c = bc % 16;
    int u  = (r == 0) ? 32 : ((r & 1) ? 32 + ((r+1) >> 1) : 32 - (r >> 1));
    int us = (u + 32) & 63;
    const float* pr = g_c1re + (long long)bc*64*33 + v;
    const float* pi = g_c1im + (long long)bc*64*33 + v;
    float re = 0.f, im = 0.f;
    for (int y = 0; y < 64; y++) {
        int m = (us*y) & 63;
        float ang = -0.09817477042468103f * (float)m;
        float s, cc; sincosf(ang, &s, &cc);
        float ar = pr[y*33], ai = pi[y*33];
        re += ar*cc - ai*s;
        im += ar*s  + ai*cc;
    }
    re *= 0.015625f;
    im *= 0.015625f;
    int n = r*33 + v;
    float* dst = g_tok + ((long long)b*NTOK + n)*32;
    dst[c]      = re;
    dst[16 + c] = im;
}

__global__ void k_shift(const float* __restrict__ cond,
                        const float* __restrict__ dcw,
                        const float* __restrict__ dcb) {
    int idx = blockIdx.x * 256 + threadIdx.x;
    if (idx >= ROWS*HD) return;
    int j = idx & (HD-1);
    int n = (idx >> 10) % NTOK;
    int b = idx / (NTOK*HD);
    if (n == 0) g_t[idx] = cond[b] * dcw[j] + dcb[j];
    else        g_t[idx] = g_buf1[idx - HD];
}

// LayerNorm on g_t -> fp16 hi (+ optional lo)
__global__ void k_ln(const float* __restrict__ g, const float* __restrict__ b,
                     int writeLo) {
    long long row = blockIdx.x;
    const float* x = g_t + row*HD;
    int tid = threadIdx.x;
    float s = 0.f, q = 0.f;
    for (int j = tid; j < HD; j += 256) { float v = x[j]; s += v; q += v*v; }
    for (int o = 16; o; o >>= 1) {
        s += __shfl_xor_sync(0xffffffffu, s, o);
        q += __shfl_xor_sync(0xffffffffu, q, o);
    }
    __shared__ float shs[8], shq[8];
    if ((tid & 31) == 0) { shs[tid >> 5] = s; shq[tid >> 5] = q; }
    __syncthreads();
    float S = 0.f, Q = 0.f;
    for (int i = 0; i < 8; i++) { S += shs[i]; Q += shq[i]; }
    float mean = S * (1.0f/HD);
    float var  = Q * (1.0f/HD) - mean*mean;
    float rstd = rsqrtf(var + 1e-5f);
    for (int j = tid; j < HD; j += 256) {
        float v = (x[j] - mean) * rstd * g[j] + b[j];
        __half h = __float2half(v);
        g_b1hi[row*HD + j] = h;
        if (writeLo) g_b1lo[row*HD + j] = __float2half(v - __half2float(h));
    }
}

// causal softmax on single-fp16 S (in place) — tail already zeroed by QK GEMM
__global__ void k_softmax() {
    int q = blockIdx.x, z = blockIdx.y;
    __half* oh = g_shi + ((long long)z*NTOK + q)*NTOK;
    int len = q + 1;
    int tid = threadIdx.x;
    float vals[9];
    int cnt = 0;
    float m = -3.4e38f;
    for (int k = tid; k < len; k += 256) {
        float v = __half2float(oh[k]);
        vals[cnt++] = v;
        m = fmaxf(m, v);
    }
    __shared__ float sh[16];
    for (int o = 16; o; o >>= 1) m = fmaxf(m, __shfl_xor_sync(0xffffffffu, m, o));
    if ((tid & 31) == 0) sh[tid >> 5] = m;
    __syncthreads();
    float M = sh[0];
    for (int i = 1; i < 8; i++) M = fmaxf(M, sh[i]);
    float s = 0.f;
    for (int i = 0; i < cnt; i++) {
        vals[i] = __expf(vals[i] - M);
        s += vals[i];
    }
    for (int o = 16; o; o >>= 1) s += __shfl_xor_sync(0xffffffffu, s, o);
    if ((tid & 31) == 0) sh[8 + (tid >> 5)] = s;
    __syncthreads();
    float T = 0.f;
    for (int i = 0; i < 8; i++) T += sh[8+i];
    float inv = 1.0f / T;
    cnt = 0;
    for (int k = tid; k < len; k += 256)
        oh[k] = __float2half(vals[cnt++] * inv);
}

// ------------------- fp32 SGEMM (init linear only, K=32) --------------------
__global__ __launch_bounds__(256)
void k_gemm32(const float* __restrict__ A, const float* __restrict__ B,
              const float* __restrict__ bias, float* __restrict__ C,
              int M, int N, int K, int lda, int ldb, int ldc)
{
    int m0 = blockIdx.y * 128, n0 = blockIdx.x * 128;
    __shared__ __align__(16) float As[8][128];
    __shared__ __align__(16) float Bs[8][128];
    float acc[8][8];
#pragma unroll
    for (int i = 0; i < 8; i++)
#pragma unroll
        for (int j = 0; j < 8; j++) acc[i][j] = 0.f;
    int tid  = threadIdx.x;
    int arow = tid >> 1,  ak = (tid & 1) << 2;
    int ty   = tid >> 4,  tx = tid & 15;
    const float* Aload = A + (long long)(m0 + arow)*lda + ak;
    bool aValid = (m0 + arow) < M;
    const float* Bload = B + (long long)(n0 + arow)*ldb + ak;
    bool bValid = (n0 + arow) < N;
    for (int k0 = 0; k0 < K; k0 += 8) {
        float4 av = aValid ? *(const float4*)(Aload + k0) : make_float4(0,0,0,0);
        As[ak+0][arow] = av.x; As[ak+1][arow] = av.y;
        As[ak+2][arow] = av.z; As[ak+3][arow] = av.w;
        float4 bv = bValid ? *(const float4*)(Bload + k0) : make_float4(0,0,0,0);
        Bs[ak+0][arow] = bv.x; Bs[ak+1][arow] = bv.y;
        Bs[ak+2][arow] = bv.z; Bs[ak+3][arow] = bv.w;
        __syncthreads();
#pragma unroll
        for (int kk = 0; kk < 8; kk++) {
            float a[8], b[8];
            *(float4*)(a)   = *(const float4*)&As[kk][ty*8];
            *(float4*)(a+4) = *(const float4*)&As[kk][ty*8+4];
            *(float4*)(b)   = *(const float4*)&Bs[kk][tx*8];
            *(float4*)(b+4) = *(const float4*)&Bs[kk][tx*8+4];
#pragma unroll
            for (int mi = 0; mi < 8; mi++)
#pragma unroll
                for (int ni = 0; ni < 8; ni++)
                    acc[mi][ni] += a[mi] * b[ni];
        }
        __syncthreads();
    }
#pragma unroll
    for (int mi = 0; mi < 8; mi++) {
        int gm = m0 + ty*8 + mi;
        if (gm >= M) continue;
#pragma unroll
        for (int ni = 0; ni < 8; ni++) {
            int gn = n0 + tx*8 + ni;
            if (gn >= N) continue;
            C[(long long)gm*ldc + gn] = acc[mi][ni] + bias[gn];
        }
    }
}

// ----------------------------------- host -----------------------------------
extern "C" void kernel_launch(void* const* d_in, const int* in_sizes, int n_in,
                              void* d_out, int out_size) {
    const float* x      = (const float*)d_in[0];
    const float* cond   = (const float*)d_in[1];
    const float* init_w = (const float*)d_in[2];
    const float* init_b = (const float*)d_in[3];
    const float* dc_w   = (const float*)d_in[4];
    const float* dc_b   = (const float*)d_in[5];
    const float* ln1_g  = (const float*)d_in[6];
    const float* ln1_b  = (const float*)d_in[7];
    const float* qkv_w  = (const float*)d_in[8];
    const float* qkv_b  = (const float*)d_in[9];
    const float* proj_w = (const float*)d_in[10];
    const float* proj_b = (const float*)d_in[11];
    const float* ln2_g  = (const float*)d_in[12];
    const float* ln2_b  = (const float*)d_in[13];
    const float* ff1_w  = (const float*)d_in[14];
    const float* ff1_b  = (const float*)d_in[15];
    const float* ff2_w  = (const float*)d_in[16];
    const float* ff2_b  = (const float*)d_in[17];
    const float* mag_w  = (const float*)d_in[18];
    const float* mag_b  = (const float*)d_in[19];
    const float* ph_w   = (const float*)d_in[20];
    const float* ph_b   = (const float*)d_in[21];
    float* out = (float*)d_out;

    float *tok, *t, *buf1, *bhd;
    cudaGetSymbolAddress((void**)&tok,  g_tok);
    cudaGetSymbolAddress((void**)&t,    g_t);
    cudaGetSymbolAddress((void**)&buf1, g_buf1);
    cudaGetSymbolAddress((void**)&bhd,  g_bhd);
    __half *qkv16,*b1h,*b1l,*qh,*kh,*vth,*shh,*aoh,*aol,
           *hidh,*hidl,*tsh,
           *wqh,*wph2,*wf1h,*wf2h,*whd;
    cudaGetSymbolAddress((void**)&qkv16,g_qkv16);
    cudaGetSymbolAddress((void**)&b1h,  g_b1hi);  cudaGetSymbolAddress((void**)&b1l,  g_b1lo);
    cudaGetSymbolAddress((void**)&qh,   g_qhi);
    cudaGetSymbolAddress((void**)&kh,   g_khi);
    cudaGetSymbolAddress((void**)&vth,  g_vthi);
    cudaGetSymbolAddress((void**)&shh,  g_shi);
    cudaGetSymbolAddress((void**)&aoh,  g_aohi);  cudaGetSymbolAddress((void**)&aol,  g_aolo);
    cudaGetSymbolAddress((void**)&hidh, g_hidhi); cudaGetSymbolAddress((void**)&hidl, g_hidlo);
    cudaGetSymbolAddress((void**)&tsh,  g_tshi);
    cudaGetSymbolAddress((void**)&wqh,  g_wqkvhi);
    cudaGetSymbolAddress((void**)&wph2, g_wprhi);
    cudaGetSymbolAddress((void**)&wf1h, g_wf1hi);
    cudaGetSymbolAddress((void**)&wf2h, g_wf2hi);
    cudaGetSymbolAddress((void**)&whd,  g_whd);

    cudaFuncSetAttribute(k_mgemm<1,0,0,0,0,0,2,1>, cudaFuncAttributeMaxDynamicSharedMemorySize, MG_SMEM);
    cudaFuncSetAttribute(k_mgemm<0,0,0,0,1,0,2,1>, cudaFuncAttributeMaxDynamicSharedMemorySize, MG_SMEM);
    cudaFuncSetAttribute(k_mgemm<0,0,0,0,0,1,1,1>, cudaFuncAttributeMaxDynamicSharedMemorySize, MG_SMEM);
    cudaFuncSetAttribute(k_mgemm<1,0,1,0,0,0,0,2>, cudaFuncAttributeMaxDynamicSharedMemorySize, MG_SMEM);
    cudaFuncSetAttribute(k_mgemm<1,1,0,0,0,0,1,2>, cudaFuncAttributeMaxDynamicSharedMemorySize, MG_SMEM);
    cudaFuncSetAttribute(k_mgemm<1,0,1,0,0,0,2,2>, cudaFuncAttributeMaxDynamicSharedMemorySize, MG_SMEM);
    cudaFuncSetAttribute(k_mgemm<1,0,0,1,0,0,0,1>, cudaFuncAttributeMaxDynamicSharedMemorySize, MG_SMEM);

    // ---- convert all weights to single fp16; gather head biases ----
    {
        long long n;
        n = (long long)LAYERS*3*HD*HD; k_split1<<<(int)((n/4+255)/256),256>>>(qkv_w,  wqh,  n);
        n = (long long)LAYERS*HD*HD;   k_split1<<<(int)((n/4+255)/256),256>>>(proj_w, wph2, n);
        n = (long long)LAYERS*4*HD*HD; k_split1<<<(int)((n/4+255)/256),256>>>(ff1_w,  wf1h, n);
        n = (long long)LAYERS*4*HD*HD; k_split1<<<(int)((n/4+255)/256),256>>>(ff2_w,  wf2h, n);
        n = (long long)16384*512;      k_split1<<<(int)((n/4+255)/256),256>>>(mag_w,  whd,  n);
        n = (long long)16384*512;      k_split1<<<(int)((n/4+255)/256),256>>>(ph_w,   whd + 16384LL*512, n);
        cudaMemcpyAsync(bhd,         mag_b, 16384*sizeof(float), cudaMemcpyDeviceToDevice);
        cudaMemcpyAsync(bhd + 16384, ph_b,  16384*sizeof(float), cudaMemcpyDeviceToDevice);
    }

    // ---- FFT + token build + init linear + shift ----
    int nfft = BATCH*16*64*33;
    k_dft1<<<(nfft+255)/256, 256>>>(x);
    k_dft2<<<(nfft+255)/256, 256>>>();
    {
        dim3 g(1024/128, ROWS/128);
        k_gemm32<<<g,256>>>(tok, init_w, init_b, buf1, ROWS, 1024, 32, 32, 32, 1024);
    }
    k_shift<<<(ROWS*HD+255)/256, 256>>>(cond, dc_w, dc_b);

    for (int l = 0; l < LAYERS; l++) {
        const float* qb  = qkv_b + l*3*HD;
        const float* pb  = proj_b + l*HD;
        const float* f1b = ff1_b + l*4*HD;
        const float* f2b = ff2_b + l*HD;
        const __half* lwqh = wqh  + (long long)l*3*HD*HD;
        const __half* lwph = wph2 + (long long)l*HD*HD;
        const __half* lw1h = wf1h + (long long)l*4*HD*HD;
        const __half* lw2h = wf2h + (long long)l*4*HD*HD;

        k_ln<<<ROWS,256>>>(ln1_g + l*HD, ln1_b + l*HD, 0);

        { // qkv (single-product, fp16 out)
            dim3 g(3072/128, ROWS/128, 1);
            k_mgemm<1,0,0,0,0,0,2,1><<<g,256,MG_SMEM>>>(
                b1h, b1h, HD, lwqh, lwqh, HD, qb, nullptr,
                nullptr, qkv16, nullptr, 3*HD,
                ROWS, 3*HD, HD, 1.f, 1, 0,0,0,0,0,0);
        }
        k_rope_split<<<ROWS,256>>>();

        { // S = alpha * Q K^T (causal, masked region zeroed in epilogue)
            dim3 g(17, 17, NZ);
            k_mgemm<0,0,0,0,1,0,2,1><<<g,256,MG_SMEM>>>(
                qh, qh, HDIM, kh, kh, HDIM, nullptr, nullptr,
                nullptr, shh, nullptr, NTOK,
                NTOK, NTOK, HDIM, 0.08838834764831845f,
                NHEADS, (long long)NHEADS*NTOK*HDIM, (long long)NTOK*HDIM,
                        (long long)NHEADS*NTOK*HDIM, (long long)NTOK*HDIM,
                        (long long)NHEADS*SZZ, SZZ);
        }
        { dim3 g(NTOK, NZ); k_softmax<<<g,256>>>(); }
        { // O = S V  (single-product, TRIK causal-K, split output attnO)
            dim3 g(1, 17, NZ);
            k_mgemm<0,0,0,0,0,1,1,1><<<g,256,MG_SMEM>>>(
                shh, shh, NTOK, vth, vth, NTOK, nullptr, nullptr,
                nullptr, aoh, aol, HD,
                NTOK, HDIM, NTOK, 1.f,
                NHEADS, (long long)NHEADS*SZZ, SZZ,
                        (long long)NHEADS*HDIM*NTOK, (long long)HDIM*NTOK,
                        (long long)NTOK*HD, (long long)HDIM);
        }
        { // proj + residual -> t  (2-product)
            dim3 g(HD/128, ROWS/128, 1);
            k_mgemm<1,0,1,0,0,0,0,2><<<g,256,MG_SMEM>>>(
                aoh, aol, HD, lwph, lwph, HD, pb, t,
                t, nullptr, nullptr, HD,
                ROWS, HD, HD, 1.f, 1, 0,0,0,0,0,0);
        }
        k_ln<<<ROWS,256>>>(ln2_g + l*HD, ln2_b + l*HD, 1);
        { // ff1 + gelu -> hid split  (2-product)
            dim3 g(4096/128, ROWS/128, 1);
            k_mgemm<1,1,0,0,0,0,1,2><<<g,256,MG_SMEM>>>(
                b1h, b1l, HD, lw1h, lw1h, HD, f1b, nullptr,
                nullptr, hidh, hidl, 4*HD,
                ROWS, 4*HD, HD, 1.f, 1, 0,0,0,0,0,0);
        }
        if (l < LAYERS-1) { // ff2 + residual -> t  (2-product)
            dim3 g(HD/128, ROWS/128, 1);
            k_mgemm<1,0,1,0,0,0,0,2><<<g,256,MG_SMEM>>>(
                hidh, hidl, 4*HD, lw2h, lw2h, 4*HD, f2b, t,
                t, nullptr, nullptr, HD,
                ROWS, HD, 4*HD, 1.f, 1, 0,0,0,0,0,0);
        } else {            // last layer: fused fp16 convert -> tsh
            dim3 g(HD/128, ROWS/128, 1);
            k_mgemm<1,0,1,0,0,0,2,2><<<g,256,MG_SMEM>>>(
                hidh, hidl, 4*HD, lw2h, lw2h, 4*HD, f2b, t,
                nullptr, tsh, nullptr, HD,
                ROWS, HD, 4*HD, 1.f, 1, 0,0,0,0,0,0);
        }
    }

    // heads: single merged launch, z in {0 = mag, 1 = phase}
    const long long HEAD_ELEMS = (long long)BATCH*16*1024*NTOK;
    {
        dim3 g(16384/128, ROWS/128, 2);
        k_mgemm<1,0,0,1,0,0,0,1><<<g,256,MG_SMEM>>>(
            tsh, tsh, HD, whd, whd, 512, bhd, nullptr,
            out, nullptr, nullptr, 0,
            ROWS, 16384, 512, 1.f,
            1, 512, 0, 16384LL*512, 0, HEAD_ELEMS, 16384);
    }
}

// round 14
// speedup vs baseline: 1.0020x; 1.0020x over previous
#include <cuda_runtime.h>
#include <cuda_fp16.h>
#include <mma.h>
#include <math.h>
#include <stdint.h>

using namespace nvcuda;

#define NTOK   2112
#define BATCH  2
#define HD     1024
#define NHEADS 8
#define HDIM   128
#define LAYERS 8
#define ROWS   (BATCH*NTOK)          // 4224
#define NZ     (BATCH*NHEADS)        // 16
#define SZZ    ((long long)NTOK*NTOK)

// ------------------------- fp32 scratch --------------------------------------
__device__ float g_c1re[BATCH*16*64*33];
__device__ float g_c1im[BATCH*16*64*33];
__device__ float g_tok [BATCH*NTOK*32];
__device__ float g_t   [ROWS*HD];
__device__ float g_buf1[ROWS*HD];
__device__ float g_qkv [ROWS*3*HD];
__device__ float g_bhd [2*16384];            // combined head biases

// ------------------------- fp16 scratch --------------------------------------
__device__ __half g_b1hi [ROWS*HD],        g_b1lo [ROWS*HD];
__device__ __half g_qhi  [NZ*NTOK*HDIM];
__device__ __half g_khi  [NZ*NTOK*HDIM];
__device__ __half g_vthi [NZ*HDIM*NTOK];
__device__ __half g_shi  [NZ*NTOK*NTOK];
__device__ __half g_aohi [ROWS*HD],        g_aolo [ROWS*HD];
__device__ __half g_hidhi[ROWS*4*HD],      g_hidlo[ROWS*4*HD];
__device__ __half g_tshi [ROWS*HD];
// weights (single fp16)
__device__ __half g_wqkvhi[LAYERS*3*HD*HD];
__device__ __half g_wprhi [LAYERS*HD*HD];
__device__ __half g_wf1hi [LAYERS*4*HD*HD];
__device__ __half g_wf2hi [LAYERS*4*HD*HD];
__device__ __half g_whd   [2LL*16384*512];   // combined mag+phase head weights

__device__ __forceinline__ float geluf(float v) {
    return 0.5f * v * (1.0f + erff(v * 0.7071067811865476f));
}
__device__ __forceinline__ uint32_t smem_u32(const void* p) {
    uint32_t a;
    asm("{ .reg .u64 t; cvta.to.shared.u64 t, %1; cvt.u32.u64 %0, t; }"
        : "=r"(a) : "l"(p));
    return a;
}
__device__ __forceinline__ void cp16(void* dst, const void* src, int srcBytes) {
    asm volatile("cp.async.cg.shared.global [%0], [%1], 16, %2;"
                 :: "r"(smem_u32(dst)), "l"(src), "r"(srcBytes) : "memory");
}
#define CP_COMMIT() asm volatile("cp.async.commit_group;" ::: "memory")
#define CP_WAIT1()  asm volatile("cp.async.wait_group 1;" ::: "memory")
#define CP_WAIT0()  asm volatile("cp.async.wait_group 0;" ::: "memory")

// ============================ wmma split-fp16 GEMM ===========================
// C = act(alpha * A B^T + bias) [+R]  (NT layout).
// PROD: 3 = AhBh+AhBl+AlBh; 2 = AhBh+AlBh (B single); 1 = AhBh (both single).
// OSPLIT: 0 = fp32 C; 1 = split fp16 Ch+Cl; 2 = single fp16 Ch.
// SCATTER: heads layout; z-batched via sCb (out stride) and sCh2 (bias stride).
// CAUSAL epilogue writes 0 above the diagonal (softmax tail pre-zeroed).
#define MG_SMEM 81920

template<int BIAS, int GELU, int RES, int SCATTER, int CAUSAL, int TRIK,
         int OSPLIT, int PROD>
__global__ __launch_bounds__(256, 2)
void k_mgemm(const __half* __restrict__ Ah_, const __half* __restrict__ Al_,
             long long lda,
             const __half* __restrict__ Bh_, const __half* __restrict__ Bl_,
             long long ldb,
             const float* __restrict__ bias, const float* __restrict__ Rres,
             float* __restrict__ C, __half* __restrict__ Ch,
             __half* __restrict__ Cl, long long ldc,
             int M, int N, int K, float alpha,
             int H, long long sAb, long long sAh2, long long sBb, long long sBh2,
             long long sCb, long long sCh2)
{
    if (CAUSAL && blockIdx.x > blockIdx.y) return;
    int m0 = blockIdx.y*128, n0 = blockIdx.x*128;
    int z = blockIdx.z; int bz = z / H, hz = z - bz*H;
    long long aoff = bz*sAb + hz*sAh2 + (long long)m0*lda;
    long long boff = bz*sBb + hz*sBh2 + (long long)n0*ldb;
    long long coff = bz*sCb + hz*sCh2;
    Ah_ += aoff; Al_ += aoff; Bh_ += boff; Bl_ += boff;
    if (SCATTER) {
        C += bz*sCb;
        if (BIAS) bias += bz*sCh2;
    } else {
        C += coff; if (OSPLIT) { Ch += coff; if (OSPLIT==1) Cl += coff; }
    }

    extern __shared__ char dsm[];
    __half* sbuf  = (__half*)dsm;            // 2 x 20480 halfs (K-loop)
    float*  stage = (float*)dsm;             // 128x128 fp32 (epilogue, aliases)

    int tid = threadIdx.x, wid = tid >> 5;
    int wm = wid & 3, wn = wid >> 2;
    int row2 = tid >> 2, seg = tid & 3;

    int mrows = M - m0; if (mrows > 128) mrows = 128;
    int nrows = N - n0; if (nrows > 128) nrows = 128;
    int Kend = TRIK ? (m0 + 128 < K ? m0 + 128 : K) : K;
    int nch = Kend >> 5;

    wmma::fragment<wmma::accumulator, 16, 16, 16, float> c[2][4];
#pragma unroll
    for (int i = 0; i < 2; i++)
#pragma unroll
        for (int j = 0; j < 4; j++) wmma::fill_fragment(c[i][j], 0.0f);

    const __half* srcs[4] = {Ah_, Al_, Bh_, Bl_};
    long long lds[2] = {lda, ldb};

    auto prefetch = [&](int chunk, int s) {
        long long k0 = (long long)chunk << 5;
        __half* base = sbuf + s*20480;
#pragma unroll
        for (int tno = 0; tno < 4; tno++) {
            if (PROD == 1 && (tno == 1 || tno == 3)) continue;
            if (PROD == 2 && tno == 3) continue;
            int lim = (tno>>1) ? nrows : mrows;
#pragma unroll
            for (int i = 0; i < 2; i++) {
                int r = row2 + 64*i;
                int v2 = (r < lim) ? 16 : 0;
                cp16(base + tno*5120 + r*40 + seg*8,
                     srcs[tno] + (long long)r*lds[tno>>1] + k0 + seg*8, v2);
            }
        }
    };

    prefetch(0, 0);
    CP_COMMIT();

    for (int i = 0; i < nch; i++) {
        if (i + 1 < nch) { prefetch(i+1, (i+1)&1); CP_COMMIT(); CP_WAIT1(); }
        else             { CP_WAIT0(); }
        __syncthreads();
        __half* b = sbuf + (i&1)*20480;
        __half* As_h = b;
        __half* As_l = b + 5120;
        __half* Bs_h = b + 10240;
        __half* Bs_l = b + 15360;
#pragma unroll
        for (int kk = 0; kk < 32; kk += 16) {
            wmma::fragment<wmma::matrix_a, 16, 16, 16, __half, wmma::row_major> fah[2], fal[2];
#pragma unroll
            for (int ii = 0; ii < 2; ii++) {
                wmma::load_matrix_sync(fah[ii], As_h + (wm*32 + ii*16)*40 + kk, 40);
                if (PROD >= 2)
                    wmma::load_matrix_sync(fal[ii], As_l + (wm*32 + ii*16)*40 + kk, 40);
            }
#pragma unroll
            for (int j = 0; j < 4; j++) {
                wmma::fragment<wmma::matrix_b, 16, 16, 16, __half, wmma::col_major> fb;
                wmma::load_matrix_sync(fb, Bs_h + (wn*64 + j*16)*40 + kk, 40);
                wmma::mma_sync(c[0][j], fah[0], fb, c[0][j]);
                wmma::mma_sync(c[1][j], fah[1], fb, c[1][j]);
                if (PROD >= 2) {
                    wmma::mma_sync(c[0][j], fal[0], fb, c[0][j]);
                    wmma::mma_sync(c[1][j], fal[1], fb, c[1][j]);
                }
                if (PROD == 3) {
                    wmma::load_matrix_sync(fb, Bs_l + (wn*64 + j*16)*40 + kk, 40);
                    wmma::mma_sync(c[0][j], fah[0], fb, c[0][j]);
                    wmma::mma_sync(c[1][j], fah[1], fb, c[1][j]);
                }
            }
        }
        __syncthreads();
    }

    // ---- single-pass epilogue: all fragments -> 128x128 fp32 stage ----
#pragma unroll
    for (int ii = 0; ii < 2; ii++)
#pragma unroll
        for (int j = 0; j < 4; j++) {
            if (SCATTER)
                wmma::store_matrix_sync(stage + (wn*64 + j*16)*128 + (wm*32 + ii*16),
                                        c[ii][j], 128, wmma::mem_col_major);
            else
                wmma::store_matrix_sync(stage + (wm*32 + ii*16)*128 + wn*64 + j*16,
                                        c[ii][j], 128, wmma::mem_row_major);
        }
    __syncthreads();
    for (int e = tid; e < 16384; e += 256) {
        int r, col;
        float v;
        if (SCATTER) { r = e & 127; col = e >> 7; v = stage[col*128 + r]; }
        else         { r = e >> 7;  col = e & 127; v = stage[e]; }
        int gm = m0 + r, gn = n0 + col;
        if (gm >= M || gn >= N) continue;
        v *= alpha;
        if (BIAS) v += bias[gn];
        if (GELU) v = geluf(v);
        if (CAUSAL && gn > gm) v = 0.f;   // pre-zero masked region for softmax/SV
        if (SCATTER) {
            int b2 = gm / NTOK;
            int nt = gm - b2*NTOK;
            long long o = ((long long)b2*16384 + (long long)(gn & 15)*1024
                           + (gn >> 4)) * NTOK + nt;
            C[o] = v;
        } else {
            long long o = (long long)gm*ldc + gn;
            if (RES) v += Rres[o];
            if (OSPLIT == 1) {
                __half hh = __float2half(v);
                Ch[o] = hh;
                Cl[o] = __float2half(v - __half2float(hh));
            } else if (OSPLIT == 2) {
                Ch[o] = __float2half(v);
            } else C[o] = v;
        }
    }
}

// ============================ elementwise kernels ============================

// hi-only fp16 convert
__global__ void k_split1(const float* __restrict__ src,
                         __half* __restrict__ hi, long long n) {
    long long i = ((long long)blockIdx.x*256 + threadIdx.x) * 4;
    if (i + 4 <= n) {
        float4 v = *(const float4*)(src + i);
        *(__half2*)(hi + i)     = __halves2half2(__float2half(v.x), __float2half(v.y));
        *(__half2*)(hi + i + 2) = __halves2half2(__float2half(v.z), __float2half(v.w));
    } else {
        for (; i < n; i++) hi[i] = __float2half(src[i]);
    }
}

// fused rope + qkv reorganize; reads fp32 qkv, writes q/k/v single fp16
__global__ void k_rope_split() {
    int row = blockIdx.x;
    int b = row / NTOK, t = row - b*NTOK;
    const float* base = g_qkv + (long long)row*3*HD;
    int tid = threadIdx.x;
    for (int idx = tid; idx < 512; idx += 256) {
        int h = idx >> 6, i = idx & 63;
        float div = expf((float)i * -0.14391156831212787f);
        float ang = (float)t * div;
        float s, c; sincosf(ang, &s, &c);
        int z = b*NHEADS + h;
        long long qi = ((long long)z*NTOK + t)*HDIM + i;
        {
            float q1 = base[h*HDIM + i], q2 = base[h*HDIM + i + 64];
            g_qhi[qi]    = __float2half(q1 + q1*c - q2*s);
            g_qhi[qi+64] = __float2half(q2 + q2*c + q1*s);
        }
        {
            float k1 = base[HD + h*HDIM + i], k2 = base[HD + h*HDIM + i + 64];
            g_khi[qi]    = __float2half(k1 + k1*c - k2*s);
            g_khi[qi+64] = __float2half(k2 + k2*c + k1*s);
        }
    }
    for (int idx = tid; idx < 1024; idx += 256) {
        int h = idx >> 7, d = idx & 127;
        int z = b*NHEADS + h;
        long long vi = ((long long)z*HDIM + d)*NTOK + t;
        g_vthi[vi] = __float2half(base[2*HD + h*HDIM + d]);
    }
}

__global__ void k_dft1(const float* __restrict__ x) {
    int idx = blockIdx.x * 256 + threadIdx.x;
    if (idx >= BATCH*16*64*33) return;
    int v  = idx % 33;
    int t  = idx / 33;
    int y  = t % 64;
    int bc = t / 64;
    const float* xr = x + ((long long)bc*64 + y)*64;
    float re = 0.f, im = 0.f;
    for (int j = 0; j < 64; j++) {
        int m = (v*j) & 63;
        float ang = -0.09817477042468103f * (float)m;
        float s, c; sincosf(ang, &s, &c);
        float xv = xr[j];
        re += xv * c;
        im += xv * s;
    }
    g_c1re[idx] = re;
    g_c1im[idx] = im;
}

__global__ void k_dft2() {
    int idx = blockIdx.x * 256 + threadIdx.x;
    if (idx >= BATCH*16*64*33) return;
    int v  = idx % 33;
    int t  = idx / 33;
    int r  = t % 64;
    int bc = t / 64;
    int b  = bc / 16, c = bc % 16;
    int u  = (r == 0) ? 32 : ((r & 1) ? 32 + ((r+1) >> 1) : 32 - (r >> 1));
    int us = (u + 32) & 63;
    const float* pr = g_c1re + (long long)bc*64*33 + v;
    const float* pi = g_c1im + (long long)bc*64*33 + v;
    float re = 0.f, im = 0.f;
    for (int y = 0; y < 64; y++) {
        int m = (us*y) & 63;
        float ang = -0.09817477042468103f * (float)m;
        float s, cc; sincosf(ang, &s, &cc);
        float ar = pr[y*33], ai = pi[y*33];
        re += ar*cc - ai*s;
        im += ar*s  + ai*cc;
    }
    re *= 0.015625f;
    im *= 0.015625f;
    int n = r*33 + v;
    float* dst = g_tok + ((long long)b*NTOK + n)*32;
    dst[c]      = re;
    dst[16 + c] = im;
}

__global__ void k_shift(const float* __restrict__ cond,
                        const float* __restrict__ dcw,
                        const float* __restrict__ dcb) {
    int idx = blockIdx.x * 256 + threadIdx.x;
    if (idx >= ROWS*HD) return;
    int j = idx & (HD-1);
    int n = (idx >> 10) % NTOK;
    int b = idx / (NTOK*HD);
    if (n == 0) g_t[idx] = cond[b] * dcw[j] + dcb[j];
    else        g_t[idx] = g_buf1[idx - HD];
}

// LayerNorm on g_t -> fp16 hi (+ optional lo)
__global__ void k_ln(const float* __restrict__ g, const float* __restrict__ b,
                     int writeLo) {
    long long row = blockIdx.x;
    const float* x = g_t + row*HD;
    int tid = threadIdx.x;
    float s = 0.f, q = 0.f;
    for (int j = tid; j < HD; j += 256) { float v = x[j]; s += v; q += v*v; }
    for (int o = 16; o; o >>= 1) {
        s += __shfl_xor_sync(0xffffffffu, s, o);
        q += __shfl_xor_sync(0xffffffffu, q, o);
    }
    __shared__ float shs[8], shq[8];
    if ((tid & 31) == 0) { shs[tid >> 5] = s; shq[tid >> 5] = q; }
    __syncthreads();
    float S = 0.f, Q = 0.f;
    for (int i = 0; i < 8; i++) { S += shs[i]; Q += shq[i]; }
    float mean = S * (1.0f/HD);
    float var  = Q * (1.0f/HD) - mean*mean;
    float rstd = rsqrtf(var + 1e-5f);
    for (int j = tid; j < HD; j += 256) {
        float v = (x[j] - mean) * rstd * g[j] + b[j];
        __half h = __float2half(v);
        g_b1hi[row*HD + j] = h;
        if (writeLo) g_b1lo[row*HD + j] = __float2half(v - __half2float(h));
    }
}

// causal softmax on single-fp16 S (in place) — tail already zeroed by QK GEMM
__global__ void k_softmax() {
    int q = blockIdx.x, z = blockIdx.y;
    __half* oh = g_shi + ((long long)z*NTOK + q)*NTOK;
    int len = q + 1;
    int tid = threadIdx.x;
    float vals[9];
    int cnt = 0;
    float m = -3.4e38f;
    for (int k = tid; k < len; k += 256) {
        float v = __half2float(oh[k]);
        vals[cnt++] = v;
        m = fmaxf(m, v);
    }
    __shared__ float sh[16];
    for (int o = 16; o; o >>= 1) m = fmaxf(m, __shfl_xor_sync(0xffffffffu, m, o));
    if ((tid & 31) == 0) sh[tid >> 5] = m;
    __syncthreads();
    float M = sh[0];
    for (int i = 1; i < 8; i++) M = fmaxf(M, sh[i]);
    float s = 0.f;
    for (int i = 0; i < cnt; i++) {
        vals[i] = __expf(vals[i] - M);
        s += vals[i];
    }
    for (int o = 16; o; o >>= 1) s += __shfl_xor_sync(0xffffffffu, s, o);
    if ((tid & 31) == 0) sh[8 + (tid >> 5)] = s;
    __syncthreads();
    float T = 0.f;
    for (int i = 0; i < 8; i++) T += sh[8+i];
    float inv = 1.0f / T;
    cnt = 0;
    for (int k = tid; k < len; k += 256)
        oh[k] = __float2half(vals[cnt++] * inv);
}

// ------------------- fp32 SGEMM (init linear only, K=32) --------------------
__global__ __launch_bounds__(256)
void k_gemm32(const float* __restrict__ A, const float* __restrict__ B,
              const float* __restrict__ bias, float* __restrict__ C,
              int M, int N, int K, int lda, int ldb, int ldc)
{
    int m0 = blockIdx.y * 128, n0 = blockIdx.x * 128;
    __shared__ __align__(16) float As[8][128];
    __shared__ __align__(16) float Bs[8][128];
    float acc[8][8];
#pragma unroll
    for (int i = 0; i < 8; i++)
#pragma unroll
        for (int j = 0; j < 8; j++) acc[i][j] = 0.f;
    int tid  = threadIdx.x;
    int arow = tid >> 1,  ak = (tid & 1) << 2;
    int ty   = tid >> 4,  tx = tid & 15;
    const float* Aload = A + (long long)(m0 + arow)*lda + ak;
    bool aValid = (m0 + arow) < M;
    const float* Bload = B + (long long)(n0 + arow)*ldb + ak;
    bool bValid = (n0 + arow) < N;
    for (int k0 = 0; k0 < K; k0 += 8) {
        float4 av = aValid ? *(const float4*)(Aload + k0) : make_float4(0,0,0,0);
        As[ak+0][arow] = av.x; As[ak+1][arow] = av.y;
        As[ak+2][arow] = av.z; As[ak+3][arow] = av.w;
        float4 bv = bValid ? *(const float4*)(Bload + k0) : make_float4(0,0,0,0);
        Bs[ak+0][arow] = bv.x; Bs[ak+1][arow] = bv.y;
        Bs[ak+2][arow] = bv.z; Bs[ak+3][arow] = bv.w;
        __syncthreads();
#pragma unroll
        for (int kk = 0; kk < 8; kk++) {
            float a[8], b[8];
            *(float4*)(a)   = *(const float4*)&As[kk][ty*8];
            *(float4*)(a+4) = *(const float4*)&As[kk][ty*8+4];
            *(float4*)(b)   = *(const float4*)&Bs[kk][tx*8];
            *(float4*)(b+4) = *(const float4*)&Bs[kk][tx*8+4];
#pragma unroll
            for (int mi = 0; mi < 8; mi++)
#pragma unroll
                for (int ni = 0; ni < 8; ni++)
                    acc[mi][ni] += a[mi] * b[ni];
        }
        __syncthreads();
    }
#pragma unroll
    for (int mi = 0; mi < 8; mi++) {
        int gm = m0 + ty*8 + mi;
        if (gm >= M) continue;
#pragma unroll
        for (int ni = 0; ni < 8; ni++) {
            int gn = n0 + tx*8 + ni;
            if (gn >= N) continue;
            C[(long long)gm*ldc + gn] = acc[mi][ni] + bias[gn];
        }
    }
}

// ----------------------------------- host -----------------------------------
extern "C" void kernel_launch(void* const* d_in, const int* in_sizes, int n_in,
                              void* d_out, int out_size) {
    const float* x      = (const float*)d_in[0];
    const float* cond   = (const float*)d_in[1];
    const float* init_w = (const float*)d_in[2];
    const float* init_b = (const float*)d_in[3];
    const float* dc_w   = (const float*)d_in[4];
    const float* dc_b   = (const float*)d_in[5];
    const float* ln1_g  = (const float*)d_in[6];
    const float* ln1_b  = (const float*)d_in[7];
    const float* qkv_w  = (const float*)d_in[8];
    const float* qkv_b  = (const float*)d_in[9];
    const float* proj_w = (const float*)d_in[10];
    const float* proj_b = (const float*)d_in[11];
    const float* ln2_g  = (const float*)d_in[12];
    const float* ln2_b  = (const float*)d_in[13];
    const float* ff1_w  = (const float*)d_in[14];
    const float* ff1_b  = (const float*)d_in[15];
    const float* ff2_w  = (const float*)d_in[16];
    const float* ff2_b  = (const float*)d_in[17];
    const float* mag_w  = (const float*)d_in[18];
    const float* mag_b  = (const float*)d_in[19];
    const float* ph_w   = (const float*)d_in[20];
    const float* ph_b   = (const float*)d_in[21];
    float* out = (float*)d_out;

    float *tok, *t, *buf1, *qkv, *bhd;
    cudaGetSymbolAddress((void**)&tok,  g_tok);
    cudaGetSymbolAddress((void**)&t,    g_t);
    cudaGetSymbolAddress((void**)&buf1, g_buf1);
    cudaGetSymbolAddress((void**)&qkv,  g_qkv);
    cudaGetSymbolAddress((void**)&bhd,  g_bhd);
    __half *b1h,*b1l,*qh,*kh,*vth,*shh,*aoh,*aol,
           *hidh,*hidl,*tsh,
           *wqh,*wph2,*wf1h,*wf2h,*whd;
    cudaGetSymbolAddress((void**)&b1h,  g_b1hi);  cudaGetSymbolAddress((void**)&b1l,  g_b1lo);
    cudaGetSymbolAddress((void**)&qh,   g_qhi);
    cudaGetSymbolAddress((void**)&kh,   g_khi);
    cudaGetSymbolAddress((void**)&vth,  g_vthi);
    cudaGetSymbolAddress((void**)&shh,  g_shi);
    cudaGetSymbolAddress((void**)&aoh,  g_aohi);  cudaGetSymbolAddress((void**)&aol,  g_aolo);
    cudaGetSymbolAddress((void**)&hidh, g_hidhi); cudaGetSymbolAddress((void**)&hidl, g_hidlo);
    cudaGetSymbolAddress((void**)&tsh,  g_tshi);
    cudaGetSymbolAddress((void**)&wqh,  g_wqkvhi);
    cudaGetSymbolAddress((void**)&wph2, g_wprhi);
    cudaGetSymbolAddress((void**)&wf1h, g_wf1hi);
    cudaGetSymbolAddress((void**)&wf2h, g_wf2hi);
    cudaGetSymbolAddress((void**)&whd,  g_whd);

    cudaFuncSetAttribute(k_mgemm<1,0,0,0,0,0,0,1>, cudaFuncAttributeMaxDynamicSharedMemorySize, MG_SMEM);
    cudaFuncSetAttribute(k_mgemm<0,0,0,0,1,0,2,1>, cudaFuncAttributeMaxDynamicSharedMemorySize, MG_SMEM);
    cudaFuncSetAttribute(k_mgemm<0,0,0,0,0,1,1,1>, cudaFuncAttributeMaxDynamicSharedMemorySize, MG_SMEM);
    cudaFuncSetAttribute(k_mgemm<1,0,1,0,0,0,0,2>, cudaFuncAttributeMaxDynamicSharedMemorySize, MG_SMEM);
    cudaFuncSetAttribute(k_mgemm<1,1,0,0,0,0,1,2>, cudaFuncAttributeMaxDynamicSharedMemorySize, MG_SMEM);
    cudaFuncSetAttribute(k_mgemm<1,0,1,0,0,0,2,2>, cudaFuncAttributeMaxDynamicSharedMemorySize, MG_SMEM);
    cudaFuncSetAttribute(k_mgemm<1,0,0,1,0,0,0,1>, cudaFuncAttributeMaxDynamicSharedMemorySize, MG_SMEM);

    // ---- convert all weights to single fp16; gather head biases ----
    {
        long long n;
        n = (long long)LAYERS*3*HD*HD; k_split1<<<(int)((n/4+255)/256),256>>>(qkv_w,  wqh,  n);
        n = (long long)LAYERS*HD*HD;   k_split1<<<(int)((n/4+255)/256),256>>>(proj_w, wph2, n);
        n = (long long)LAYERS*4*HD*HD; k_split1<<<(int)((n/4+255)/256),256>>>(ff1_w,  wf1h, n);
        n = (long long)LAYERS*4*HD*HD; k_split1<<<(int)((n/4+255)/256),256>>>(ff2_w,  wf2h, n);
        n = (long long)16384*512;      k_split1<<<(int)((n/4+255)/256),256>>>(mag_w,  whd,  n);
        n = (long long)16384*512;      k_split1<<<(int)((n/4+255)/256),256>>>(ph_w,   whd + 16384LL*512, n);
        cudaMemcpyAsync(bhd,         mag_b, 16384*sizeof(float), cudaMemcpyDeviceToDevice);
        cudaMemcpyAsync(bhd + 16384, ph_b,  16384*sizeof(float), cudaMemcpyDeviceToDevice);
    }

    // ---- FFT + token build + init linear + shift ----
    int nfft = BATCH*16*64*33;
    k_dft1<<<(nfft+255)/256, 256>>>(x);
    k_dft2<<<(nfft+255)/256, 256>>>();
    {
        dim3 g(1024/128, ROWS/128);
        k_gemm32<<<g,256>>>(tok, init_w, init_b, buf1, ROWS, 1024, 32, 32, 32, 1024);
    }
    k_shift<<<(ROWS*HD+255)/256, 256>>>(cond, dc_w, dc_b);

    for (int l = 0; l < LAYERS; l++) {
        const float* qb  = qkv_b + l*3*HD;
        const float* pb  = proj_b + l*HD;
        const float* f1b = ff1_b + l*4*HD;
        const float* f2b = ff2_b + l*HD;
        const __half* lwqh = wqh  + (long long)l*3*HD*HD;
        const __half* lwph = wph2 + (long long)l*HD*HD;
        const __half* lw1h = wf1h + (long long)l*4*HD*HD;
        const __half* lw2h = wf2h + (long long)l*4*HD*HD;

        k_ln<<<ROWS,256>>>(ln1_g + l*HD, ln1_b + l*HD, 0);

        { // qkv (single-product, fp32 out — R12 numerics)
            dim3 g(3072/128, ROWS/128, 1);
            k_mgemm<1,0,0,0,0,0,0,1><<<g,256,MG_SMEM>>>(
                b1h, b1h, HD, lwqh, lwqh, HD, qb, nullptr,
                qkv, nullptr, nullptr, 3*HD,
                ROWS, 3*HD, HD, 1.f, 1, 0,0,0,0,0,0);
        }
        k_rope_split<<<ROWS,256>>>();

        { // S = alpha * Q K^T (causal; masked region zeroed in epilogue)
            dim3 g(17, 17, NZ);
            k_mgemm<0,0,0,0,1,0,2,1><<<g,256,MG_SMEM>>>(
                qh, qh, HDIM, kh, kh, HDIM, nullptr, nullptr,
                nullptr, shh, nullptr, NTOK,
                NTOK, NTOK, HDIM, 0.08838834764831845f,
                NHEADS, (long long)NHEADS*NTOK*HDIM, (long long)NTOK*HDIM,
                        (long long)NHEADS*NTOK*HDIM, (long long)NTOK*HDIM,
                        (long long)NHEADS*SZZ, SZZ);
        }
        { dim3 g(NTOK, NZ); k_softmax<<<g,256>>>(); }
        { // O = S V  (single-product, TRIK causal-K, split output attnO)
            dim3 g(1, 17, NZ);
            k_mgemm<0,0,0,0,0,1,1,1><<<g,256,MG_SMEM>>>(
                shh, shh, NTOK, vth, vth, NTOK, nullptr, nullptr,
                nullptr, aoh, aol, HD,
                NTOK, HDIM, NTOK, 1.f,
                NHEADS, (long long)NHEADS*SZZ, SZZ,
                        (long long)NHEADS*HDIM*NTOK, (long long)HDIM*NTOK,
                        (long long)NTOK*HD, (long long)HDIM);
        }
        { // proj + residual -> t  (2-product)
            dim3 g(HD/128, ROWS/128, 1);
            k_mgemm<1,0,1,0,0,0,0,2><<<g,256,MG_SMEM>>>(
                aoh, aol, HD, lwph, lwph, HD, pb, t,
                t, nullptr, nullptr, HD,
                ROWS, HD, HD, 1.f, 1, 0,0,0,0,0,0);
        }
        k_ln<<<ROWS,256>>>(ln2_g + l*HD, ln2_b + l*HD, 1);
        { // ff1 + gelu -> hid split  (2-product)
            dim3 g(4096/128, ROWS/128, 1);
            k_mgemm<1,1,0,0,0,0,1,2><<<g,256,MG_SMEM>>>(
                b1h, b1l, HD, lw1h, lw1h, HD, f1b, nullptr,
                nullptr, hidh, hidl, 4*HD,
                ROWS, 4*HD, HD, 1.f, 1, 0,0,0,0,0,0);
        }
        if (l < LAYERS-1) { // ff2 + residual -> t  (2-product)
            dim3 g(HD/128, ROWS/128, 1);
            k_mgemm<1,0,1,0,0,0,0,2><<<g,256,MG_SMEM>>>(
                hidh, hidl, 4*HD, lw2h, lw2h, 4*HD, f2b, t,
                t, nullptr, nullptr, HD,
                ROWS, HD, 4*HD, 1.f, 1, 0,0,0,0,0,0);
        } else {            // last layer: fused fp16 convert -> tsh (exact)
            dim3 g(HD/128, ROWS/128, 1);
            k_mgemm<1,0,1,0,0,0,2,2><<<g,256,MG_SMEM>>>(
                hidh, hidl, 4*HD, lw2h, lw2h, 4*HD, f2b, t,
                nullptr, tsh, nullptr, HD,
                ROWS, HD, 4*HD, 1.f, 1, 0,0,0,0,0,0);
        }
    }

    // heads: single merged launch, z in {0 = mag, 1 = phase}
    const long long HEAD_ELEMS = (long long)BATCH*16*1024*NTOK;
    {
        dim3 g(16384/128, ROWS/128, 2);
        k_mgemm<1,0,0,1,0,0,0,1><<<g,256,MG_SMEM>>>(
            tsh, tsh, HD, whd, whd, 512, bhd, nullptr,
            out, nullptr, nullptr, 0,
            ROWS, 16384, 512, 1.f,
            1, 512, 0, 16384LL*512, 0, HEAD_ELEMS, 16384);
    }
}

// round 15
// speedup vs baseline: 1.1087x; 1.1066x over previous
#include <cuda_runtime.h>
#include <cuda_fp16.h>
#include <mma.h>
#include <math.h>
#include <stdint.h>

using namespace nvcuda;

#define NTOK   2112
#define BATCH  2
#define HD     1024
#define NHEADS 8
#define HDIM   128
#define LAYERS 8
#define ROWS   (BATCH*NTOK)          // 4224
#define NZ     (BATCH*NHEADS)        // 16
#define SZZ    ((long long)NTOK*NTOK)

// ------------------------- fp32 scratch --------------------------------------
__device__ float g_c1re[BATCH*16*64*33];
__device__ float g_c1im[BATCH*16*64*33];
__device__ float g_tok [BATCH*NTOK*32];
__device__ float g_t   [ROWS*HD];
__device__ float g_buf1[ROWS*HD];
__device__ float g_qkv [ROWS*3*HD];
__device__ float g_bhd [2*16384];            // combined head biases

// ------------------------- fp16 scratch --------------------------------------
__device__ __half g_b1hi [ROWS*HD],        g_b1lo [ROWS*HD];
__device__ __half g_qhi  [NZ*NTOK*HDIM];
__device__ __half g_khi  [NZ*NTOK*HDIM];
__device__ __half g_vthi [NZ*HDIM*NTOK];
__device__ __half g_shi  [NZ*NTOK*NTOK];
__device__ __half g_aohi [ROWS*HD];
__device__ __half g_hidhi[ROWS*4*HD],      g_hidlo[ROWS*4*HD];
__device__ __half g_tshi [ROWS*HD];
// weights (single fp16)
__device__ __half g_wqkvhi[LAYERS*3*HD*HD];
__device__ __half g_wprhi [LAYERS*HD*HD];
__device__ __half g_wf1hi [LAYERS*4*HD*HD];
__device__ __half g_wf2hi [LAYERS*4*HD*HD];
__device__ __half g_whd   [2LL*16384*512];   // combined mag+phase head weights

__device__ __forceinline__ float geluf(float v) {
    return 0.5f * v * (1.0f + erff(v * 0.7071067811865476f));
}
__device__ __forceinline__ uint32_t smem_u32(const void* p) {
    uint32_t a;
    asm("{ .reg .u64 t; cvta.to.shared.u64 t, %1; cvt.u32.u64 %0, t; }"
        : "=r"(a) : "l"(p));
    return a;
}
__device__ __forceinline__ void cp16(void* dst, const void* src, int srcBytes) {
    asm volatile("cp.async.cg.shared.global [%0], [%1], 16, %2;"
                 :: "r"(smem_u32(dst)), "l"(src), "r"(srcBytes) : "memory");
}
#define CP_COMMIT() asm volatile("cp.async.commit_group;" ::: "memory")
#define CP_WAIT1()  asm volatile("cp.async.wait_group 1;" ::: "memory")
#define CP_WAIT0()  asm volatile("cp.async.wait_group 0;" ::: "memory")

// ============================ wmma split-fp16 GEMM ===========================
// C = act(alpha * A B^T + bias) [+R]  (NT layout).
// PROD: 3 = AhBh+AhBl+AlBh; 2 = AhBh+AlBh (B single); 1 = AhBh (both single).
// OSPLIT: 0 = fp32 C; 1 = split fp16 Ch+Cl; 2 = single fp16 Ch.
// SCATTER: heads layout; z-batched via sCb (out stride) and sCh2 (bias stride).
// CAUSAL epilogue writes 0 above the diagonal (softmax tail pre-zeroed).
#define MG_SMEM 81920

template<int BIAS, int GELU, int RES, int SCATTER, int CAUSAL, int TRIK,
         int OSPLIT, int PROD>
__global__ __launch_bounds__(256, 2)
void k_mgemm(const __half* __restrict__ Ah_, const __half* __restrict__ Al_,
             long long lda,
             const __half* __restrict__ Bh_, const __half* __restrict__ Bl_,
             long long ldb,
             const float* __restrict__ bias, const float* __restrict__ Rres,
             float* __restrict__ C, __half* __restrict__ Ch,
             __half* __restrict__ Cl, long long ldc,
             int M, int N, int K, float alpha,
             int H, long long sAb, long long sAh2, long long sBb, long long sBh2,
             long long sCb, long long sCh2)
{
    if (CAUSAL && blockIdx.x > blockIdx.y) return;
    int m0 = blockIdx.y*128, n0 = blockIdx.x*128;
    int z = blockIdx.z; int bz = z / H, hz = z - bz*H;
    long long aoff = bz*sAb + hz*sAh2 + (long long)m0*lda;
    long long boff = bz*sBb + hz*sBh2 + (long long)n0*ldb;
    long long coff = bz*sCb + hz*sCh2;
    Ah_ += aoff; Al_ += aoff; Bh_ += boff; Bl_ += boff;
    if (SCATTER) {
        C += bz*sCb;
        if (BIAS) bias += bz*sCh2;
    } else {
        C += coff; if (OSPLIT) { Ch += coff; if (OSPLIT==1) Cl += coff; }
    }

    extern __shared__ char dsm[];
    __half* sbuf  = (__half*)dsm;            // 2 x 20480 halfs (K-loop)
    float*  stage = (float*)dsm;             // 128x128 fp32 (epilogue, aliases)

    int tid = threadIdx.x, wid = tid >> 5;
    int wm = wid & 3, wn = wid >> 2;
    int row2 = tid >> 2, seg = tid & 3;

    int mrows = M - m0; if (mrows > 128) mrows = 128;
    int nrows = N - n0; if (nrows > 128) nrows = 128;
    int Kend = TRIK ? (m0 + 128 < K ? m0 + 128 : K) : K;
    int nch = Kend >> 5;

    wmma::fragment<wmma::accumulator, 16, 16, 16, float> c[2][4];
#pragma unroll
    for (int i = 0; i < 2; i++)
#pragma unroll
        for (int j = 0; j < 4; j++) wmma::fill_fragment(c[i][j], 0.0f);

    const __half* srcs[4] = {Ah_, Al_, Bh_, Bl_};
    long long lds[2] = {lda, ldb};

    auto prefetch = [&](int chunk, int s) {
        long long k0 = (long long)chunk << 5;
        __half* base = sbuf + s*20480;
#pragma unroll
        for (int tno = 0; tno < 4; tno++) {
            if (PROD == 1 && (tno == 1 || tno == 3)) continue;
            if (PROD == 2 && tno == 3) continue;
            int lim = (tno>>1) ? nrows : mrows;
#pragma unroll
            for (int i = 0; i < 2; i++) {
                int r = row2 + 64*i;
                int v2 = (r < lim) ? 16 : 0;
                cp16(base + tno*5120 + r*40 + seg*8,
                     srcs[tno] + (long long)r*lds[tno>>1] + k0 + seg*8, v2);
            }
        }
    };

    prefetch(0, 0);
    CP_COMMIT();

    for (int i = 0; i < nch; i++) {
        if (i + 1 < nch) { prefetch(i+1, (i+1)&1); CP_COMMIT(); CP_WAIT1(); }
        else             { CP_WAIT0(); }
        __syncthreads();
        __half* b = sbuf + (i&1)*20480;
        __half* As_h = b;
        __half* As_l = b + 5120;
        __half* Bs_h = b + 10240;
        __half* Bs_l = b + 15360;
#pragma unroll
        for (int kk = 0; kk < 32; kk += 16) {
            wmma::fragment<wmma::matrix_a, 16, 16, 16, __half, wmma::row_major> fah[2], fal[2];
#pragma unroll
            for (int ii = 0; ii < 2; ii++) {
                wmma::load_matrix_sync(fah[ii], As_h + (wm*32 + ii*16)*40 + kk, 40);
                if (PROD >= 2)
                    wmma::load_matrix_sync(fal[ii], As_l + (wm*32 + ii*16)*40 + kk, 40);
            }
#pragma unroll
            for (int j = 0; j < 4; j++) {
                wmma::fragment<wmma::matrix_b, 16, 16, 16, __half, wmma::col_major> fb;
                wmma::load_matrix_sync(fb, Bs_h + (wn*64 + j*16)*40 + kk, 40);
                wmma::mma_sync(c[0][j], fah[0], fb, c[0][j]);
                wmma::mma_sync(c[1][j], fah[1], fb, c[1][j]);
                if (PROD >= 2) {
                    wmma::mma_sync(c[0][j], fal[0], fb, c[0][j]);
                    wmma::mma_sync(c[1][j], fal[1], fb, c[1][j]);
                }
                if (PROD == 3) {
                    wmma::load_matrix_sync(fb, Bs_l + (wn*64 + j*16)*40 + kk, 40);
                    wmma::mma_sync(c[0][j], fah[0], fb, c[0][j]);
                    wmma::mma_sync(c[1][j], fah[1], fb, c[1][j]);
                }
            }
        }
        __syncthreads();
    }

    // ---- single-pass epilogue: all fragments -> 128x128 fp32 stage ----
#pragma unroll
    for (int ii = 0; ii < 2; ii++)
#pragma unroll
        for (int j = 0; j < 4; j++) {
            if (SCATTER)
                wmma::store_matrix_sync(stage + (wn*64 + j*16)*128 + (wm*32 + ii*16),
                                        c[ii][j], 128, wmma::mem_col_major);
            else
                wmma::store_matrix_sync(stage + (wm*32 + ii*16)*128 + wn*64 + j*16,
                                        c[ii][j], 128, wmma::mem_row_major);
        }
    __syncthreads();
    for (int e = tid; e < 16384; e += 256) {
        int r, col;
        float v;
        if (SCATTER) { r = e & 127; col = e >> 7; v = stage[col*128 + r]; }
        else         { r = e >> 7;  col = e & 127; v = stage[e]; }
        int gm = m0 + r, gn = n0 + col;
        if (gm >= M || gn >= N) continue;
        v *= alpha;
        if (BIAS) v += bias[gn];
        if (GELU) v = geluf(v);
        if (CAUSAL && gn > gm) v = 0.f;   // pre-zero masked region for softmax/SV
        if (SCATTER) {
            int b2 = gm / NTOK;
            int nt = gm - b2*NTOK;
            long long o = ((long long)b2*16384 + (long long)(gn & 15)*1024
                           + (gn >> 4)) * NTOK + nt;
            C[o] = v;
        } else {
            long long o = (long long)gm*ldc + gn;
            if (RES) v += Rres[o];
            if (OSPLIT == 1) {
                __half hh = __float2half(v);
                Ch[o] = hh;
                Cl[o] = __float2half(v - __half2float(hh));
            } else if (OSPLIT == 2) {
                Ch[o] = __float2half(v);
            } else C[o] = v;
        }
    }
}

// ============================ elementwise kernels ============================

// hi-only fp16 convert
__global__ void k_split1(const float* __restrict__ src,
                         __half* __restrict__ hi, long long n) {
    long long i = ((long long)blockIdx.x*256 + threadIdx.x) * 4;
    if (i + 4 <= n) {
        float4 v = *(const float4*)(src + i);
        *(__half2*)(hi + i)     = __halves2half2(__float2half(v.x), __float2half(v.y));
        *(__half2*)(hi + i + 2) = __halves2half2(__float2half(v.z), __float2half(v.w));
    } else {
        for (; i < n; i++) hi[i] = __float2half(src[i]);
    }
}

// fused rope + qkv reorganize; reads fp32 qkv, writes q/k/v single fp16
__global__ void k_rope_split() {
    int row = blockIdx.x;
    int b = row / NTOK, t = row - b*NTOK;
    const float* base = g_qkv + (long long)row*3*HD;
    int tid = threadIdx.x;
    for (int idx = tid; idx < 512; idx += 256) {
        int h = idx >> 6, i = idx & 63;
        float div = expf((float)i * -0.14391156831212787f);
        float ang = (float)t * div;
        float s, c; sincosf(ang, &s, &c);
        int z = b*NHEADS + h;
        long long qi = ((long long)z*NTOK + t)*HDIM + i;
        {
            float q1 = base[h*HDIM + i], q2 = base[h*HDIM + i + 64];
            g_qhi[qi]    = __float2half(q1 + q1*c - q2*s);
            g_qhi[qi+64] = __float2half(q2 + q2*c + q1*s);
        }
        {
            float k1 = base[HD + h*HDIM + i], k2 = base[HD + h*HDIM + i + 64];
            g_khi[qi]    = __float2half(k1 + k1*c - k2*s);
            g_khi[qi+64] = __float2half(k2 + k2*c + k1*s);
        }
    }
    for (int idx = tid; idx < 1024; idx += 256) {
        int h = idx >> 7, d = idx & 127;
        int z = b*NHEADS + h;
        long long vi = ((long long)z*HDIM + d)*NTOK + t;
        g_vthi[vi] = __float2half(base[2*HD + h*HDIM + d]);
    }
}

__global__ void k_dft1(const float* __restrict__ x) {
    int idx = blockIdx.x * 256 + threadIdx.x;
    if (idx >= BATCH*16*64*33) return;
    int v  = idx % 33;
    int t  = idx / 33;
    int y  = t % 64;
    int bc = t / 64;
    const float* xr = x + ((long long)bc*64 + y)*64;
    float re = 0.f, im = 0.f;
    for (int j = 0; j < 64; j++) {
        int m = (v*j) & 63;
        float ang = -0.09817477042468103f * (float)m;
        float s, c; sincosf(ang, &s, &c);
        float xv = xr[j];
        re += xv * c;
        im += xv * s;
    }
    g_c1re[idx] = re;
    g_c1im[idx] = im;
}

__global__ void k_dft2() {
    int idx = blockIdx.x * 256 + threadIdx.x;
    if (idx >= BATCH*16*64*33) return;
    int v  = idx % 33;
    int t  = idx / 33;
    int r  = t % 64;
    int bc = t / 64;
    int b  = bc / 16, c = bc % 16;
    int u  = (r == 0) ? 32 : ((r & 1) ? 32 + ((r+1) >> 1) : 32 - (r >> 1));
    int us = (u + 32) & 63;
    const float* pr = g_c1re + (long long)bc*64*33 + v;
    const float* pi = g_c1im + (long long)bc*64*33 + v;
    float re = 0.f, im = 0.f;
    for (int y = 0; y < 64; y++) {
        int m = (us*y) & 63;
        float ang = -0.09817477042468103f * (float)m;
        float s, cc; sincosf(ang, &s, &cc);
        float ar = pr[y*33], ai = pi[y*33];
        re += ar*cc - ai*s;
        im += ar*s  + ai*cc;
    }
    re *= 0.015625f;
    im *= 0.015625f;
    int n = r*33 + v;
    float* dst = g_tok + ((long long)b*NTOK + n)*32;
    dst[c]      = re;
    dst[16 + c] = im;
}

__global__ void k_shift(const float* __restrict__ cond,
                        const float* __restrict__ dcw,
                        const float* __restrict__ dcb) {
    int idx = blockIdx.x * 256 + threadIdx.x;
    if (idx >= ROWS*HD) return;
    int j = idx & (HD-1);
    int n = (idx >> 10) % NTOK;
    int b = idx / (NTOK*HD);
    if (n == 0) g_t[idx] = cond[b] * dcw[j] + dcb[j];
    else        g_t[idx] = g_buf1[idx - HD];
}

// LayerNorm on g_t -> fp16 hi (+ optional lo)
__global__ void k_ln(const float* __restrict__ g, const float* __restrict__ b,
                     int writeLo) {
    long long row = blockIdx.x;
    const float* x = g_t + row*HD;
    int tid = threadIdx.x;
    float s = 0.f, q = 0.f;
    for (int j = tid; j < HD; j += 256) { float v = x[j]; s += v; q += v*v; }
    for (int o = 16; o; o >>= 1) {
        s += __shfl_xor_sync(0xffffffffu, s, o);
        q += __shfl_xor_sync(0xffffffffu, q, o);
    }
    __shared__ float shs[8], shq[8];
    if ((tid & 31) == 0) { shs[tid >> 5] = s; shq[tid >> 5] = q; }
    __syncthreads();
    float S = 0.f, Q = 0.f;
    for (int i = 0; i < 8; i++) { S += shs[i]; Q += shq[i]; }
    float mean = S * (1.0f/HD);
    float var  = Q * (1.0f/HD) - mean*mean;
    float rstd = rsqrtf(var + 1e-5f);
    for (int j = tid; j < HD; j += 256) {
        float v = (x[j] - mean) * rstd * g[j] + b[j];
        __half h = __float2half(v);
        g_b1hi[row*HD + j] = h;
        if (writeLo) g_b1lo[row*HD + j] = __float2half(v - __half2float(h));
    }
}

// causal softmax on single-fp16 S (in place) — tail already zeroed by QK GEMM
__global__ void k_softmax() {
    int q = blockIdx.x, z = blockIdx.y;
    __half* oh = g_shi + ((long long)z*NTOK + q)*NTOK;
    int len = q + 1;
    int tid = threadIdx.x;
    float vals[9];
    int cnt = 0;
    float m = -3.4e38f;
    for (int k = tid; k < len; k += 256) {
        float v = __half2float(oh[k]);
        vals[cnt++] = v;
        m = fmaxf(m, v);
    }
    __shared__ float sh[16];
    for (int o = 16; o; o >>= 1) m = fmaxf(m, __shfl_xor_sync(0xffffffffu, m, o));
    if ((tid & 31) == 0) sh[tid >> 5] = m;
    __syncthreads();
    float M = sh[0];
    for (int i = 1; i < 8; i++) M = fmaxf(M, sh[i]);
    float s = 0.f;
    for (int i = 0; i < cnt; i++) {
        vals[i] = __expf(vals[i] - M);
        s += vals[i];
    }
    for (int o = 16; o; o >>= 1) s += __shfl_xor_sync(0xffffffffu, s, o);
    if ((tid & 31) == 0) sh[8 + (tid >> 5)] = s;
    __syncthreads();
    float T = 0.f;
    for (int i = 0; i < 8; i++) T += sh[8+i];
    float inv = 1.0f / T;
    cnt = 0;
    for (int k = tid; k < len; k += 256)
        oh[k] = __float2half(vals[cnt++] * inv);
}

// ------------------- fp32 SGEMM (init linear only, K=32) --------------------
__global__ __launch_bounds__(256)
void k_gemm32(const float* __restrict__ A, const float* __restrict__ B,
              const float* __restrict__ bias, float* __restrict__ C,
              int M, int N, int K, int lda, int ldb, int ldc)
{
    int m0 = blockIdx.y * 128, n0 = blockIdx.x * 128;
    __shared__ __align__(16) float As[8][128];
    __shared__ __align__(16) float Bs[8][128];
    float acc[8][8];
#pragma unroll
    for (int i = 0; i < 8; i++)
#pragma unroll
        for (int j = 0; j < 8; j++) acc[i][j] = 0.f;
    int tid  = threadIdx.x;
    int arow = tid >> 1,  ak = (tid & 1) << 2;
    int ty   = tid >> 4,  tx = tid & 15;
    const float* Aload = A + (long long)(m0 + arow)*lda + ak;
    bool aValid = (m0 + arow) < M;
    const float* Bload = B + (long long)(n0 + arow)*ldb + ak;
    bool bValid = (n0 + arow) < N;
    for (int k0 = 0; k0 < K; k0 += 8) {
        float4 av = aValid ? *(const float4*)(Aload + k0) : make_float4(0,0,0,0);
        As[ak+0][arow] = av.x; As[ak+1][arow] = av.y;
        As[ak+2][arow] = av.z; As[ak+3][arow] = av.w;
        float4 bv = bValid ? *(const float4*)(Bload + k0) : make_float4(0,0,0,0);
        Bs[ak+0][arow] = bv.x; Bs[ak+1][arow] = bv.y;
        Bs[ak+2][arow] = bv.z; Bs[ak+3][arow] = bv.w;
        __syncthreads();
#pragma unroll
        for (int kk = 0; kk < 8; kk++) {
            float a[8], b[8];
            *(float4*)(a)   = *(const float4*)&As[kk][ty*8];
            *(float4*)(a+4) = *(const float4*)&As[kk][ty*8+4];
            *(float4*)(b)   = *(const float4*)&Bs[kk][tx*8];
            *(float4*)(b+4) = *(const float4*)&Bs[kk][tx*8+4];
#pragma unroll
            for (int mi = 0; mi < 8; mi++)
#pragma unroll
                for (int ni = 0; ni < 8; ni++)
                    acc[mi][ni] += a[mi] * b[ni];
        }
        __syncthreads();
    }
#pragma unroll
    for (int mi = 0; mi < 8; mi++) {
        int gm = m0 + ty*8 + mi;
        if (gm >= M) continue;
#pragma unroll
        for (int ni = 0; ni < 8; ni++) {
            int gn = n0 + tx*8 + ni;
            if (gn >= N) continue;
            C[(long long)gm*ldc + gn] = acc[mi][ni] + bias[gn];
        }
    }
}

// ----------------------------------- host -----------------------------------
extern "C" void kernel_launch(void* const* d_in, const int* in_sizes, int n_in,
                              void* d_out, int out_size) {
    const float* x      = (const float*)d_in[0];
    const float* cond   = (const float*)d_in[1];
    const float* init_w = (const float*)d_in[2];
    const float* init_b = (const float*)d_in[3];
    const float* dc_w   = (const float*)d_in[4];
    const float* dc_b   = (const float*)d_in[5];
    const float* ln1_g  = (const float*)d_in[6];
    const float* ln1_b  = (const float*)d_in[7];
    const float* qkv_w  = (const float*)d_in[8];
    const float* qkv_b  = (const float*)d_in[9];
    const float* proj_w = (const float*)d_in[10];
    const float* proj_b = (const float*)d_in[11];
    const float* ln2_g  = (const float*)d_in[12];
    const float* ln2_b  = (const float*)d_in[13];
    const float* ff1_w  = (const float*)d_in[14];
    const float* ff1_b  = (const float*)d_in[15];
    const float* ff2_w  = (const float*)d_in[16];
    const float* ff2_b  = (const float*)d_in[17];
    const float* mag_w  = (const float*)d_in[18];
    const float* mag_b  = (const float*)d_in[19];
    const float* ph_w   = (const float*)d_in[20];
    const float* ph_b   = (const float*)d_in[21];
    float* out = (float*)d_out;

    float *tok, *t, *buf1, *qkv, *bhd;
    cudaGetSymbolAddress((void**)&tok,  g_tok);
    cudaGetSymbolAddress((void**)&t,    g_t);
    cudaGetSymbolAddress((void**)&buf1, g_buf1);
    cudaGetSymbolAddress((void**)&qkv,  g_qkv);
    cudaGetSymbolAddress((void**)&bhd,  g_bhd);
    __half *b1h,*b1l,*qh,*kh,*vth,*shh,*aoh,
           *hidh,*hidl,*tsh,
           *wqh,*wph2,*wf1h,*wf2h,*whd;
    cudaGetSymbolAddress((void**)&b1h,  g_b1hi);  cudaGetSymbolAddress((void**)&b1l,  g_b1lo);
    cudaGetSymbolAddress((void**)&qh,   g_qhi);
    cudaGetSymbolAddress((void**)&kh,   g_khi);
    cudaGetSymbolAddress((void**)&vth,  g_vthi);
    cudaGetSymbolAddress((void**)&shh,  g_shi);
    cudaGetSymbolAddress((void**)&aoh,  g_aohi);
    cudaGetSymbolAddress((void**)&hidh, g_hidhi); cudaGetSymbolAddress((void**)&hidl, g_hidlo);
    cudaGetSymbolAddress((void**)&tsh,  g_tshi);
    cudaGetSymbolAddress((void**)&wqh,  g_wqkvhi);
    cudaGetSymbolAddress((void**)&wph2, g_wprhi);
    cudaGetSymbolAddress((void**)&wf1h, g_wf1hi);
    cudaGetSymbolAddress((void**)&wf2h, g_wf2hi);
    cudaGetSymbolAddress((void**)&whd,  g_whd);

    cudaFuncSetAttribute(k_mgemm<1,0,0,0,0,0,0,1>, cudaFuncAttributeMaxDynamicSharedMemorySize, MG_SMEM);
    cudaFuncSetAttribute(k_mgemm<0,0,0,0,1,0,2,1>, cudaFuncAttributeMaxDynamicSharedMemorySize, MG_SMEM);
    cudaFuncSetAttribute(k_mgemm<0,0,0,0,0,1,2,1>, cudaFuncAttributeMaxDynamicSharedMemorySize, MG_SMEM);
    cudaFuncSetAttribute(k_mgemm<1,0,1,0,0,0,0,1>, cudaFuncAttributeMaxDynamicSharedMemorySize, MG_SMEM);
    cudaFuncSetAttribute(k_mgemm<1,1,0,0,0,0,1,1>, cudaFuncAttributeMaxDynamicSharedMemorySize, MG_SMEM);
    cudaFuncSetAttribute(k_mgemm<1,0,1,0,0,0,0,2>, cudaFuncAttributeMaxDynamicSharedMemorySize, MG_SMEM);
    cudaFuncSetAttribute(k_mgemm<1,0,1,0,0,0,2,2>, cudaFuncAttributeMaxDynamicSharedMemorySize, MG_SMEM);
    cudaFuncSetAttribute(k_mgemm<1,0,0,1,0,0,0,1>, cudaFuncAttributeMaxDynamicSharedMemorySize, MG_SMEM);

    // ---- convert all weights to single fp16; gather head biases ----
    {
        long long n;
        n = (long long)LAYERS*3*HD*HD; k_split1<<<(int)((n/4+255)/256),256>>>(qkv_w,  wqh,  n);
        n = (long long)LAYERS*HD*HD;   k_split1<<<(int)((n/4+255)/256),256>>>(proj_w, wph2, n);
        n = (long long)LAYERS*4*HD*HD; k_split1<<<(int)((n/4+255)/256),256>>>(ff1_w,  wf1h, n);
        n = (long long)LAYERS*4*HD*HD; k_split1<<<(int)((n/4+255)/256),256>>>(ff2_w,  wf2h, n);
        n = (long long)16384*512;      k_split1<<<(int)((n/4+255)/256),256>>>(mag_w,  whd,  n);
        n = (long long)16384*512;      k_split1<<<(int)((n/4+255)/256),256>>>(ph_w,   whd + 16384LL*512, n);
        cudaMemcpyAsync(bhd,         mag_b, 16384*sizeof(float), cudaMemcpyDeviceToDevice);
        cudaMemcpyAsync(bhd + 16384, ph_b,  16384*sizeof(float), cudaMemcpyDeviceToDevice);
    }

    // ---- FFT + token build + init linear + shift ----
    int nfft = BATCH*16*64*33;
    k_dft1<<<(nfft+255)/256, 256>>>(x);
    k_dft2<<<(nfft+255)/256, 256>>>();
    {
        dim3 g(1024/128, ROWS/128);
        k_gemm32<<<g,256>>>(tok, init_w, init_b, buf1, ROWS, 1024, 32, 32, 32, 1024);
    }
    k_shift<<<(ROWS*HD+255)/256, 256>>>(cond, dc_w, dc_b);

    for (int l = 0; l < LAYERS; l++) {
        const float* qb  = qkv_b + l*3*HD;
        const float* pb  = proj_b + l*HD;
        const float* f1b = ff1_b + l*4*HD;
        const float* f2b = ff2_b + l*HD;
        const __half* lwqh = wqh  + (long long)l*3*HD*HD;
        const __half* lwph = wph2 + (long long)l*HD*HD;
        const __half* lw1h = wf1h + (long long)l*4*HD*HD;
        const __half* lw2h = wf2h + (long long)l*4*HD*HD;

        k_ln<<<ROWS,256>>>(ln1_g + l*HD, ln1_b + l*HD, 0);

        { // qkv (single-product, fp32 out)
            dim3 g(3072/128, ROWS/128, 1);
            k_mgemm<1,0,0,0,0,0,0,1><<<g,256,MG_SMEM>>>(
                b1h, b1h, HD, lwqh, lwqh, HD, qb, nullptr,
                qkv, nullptr, nullptr, 3*HD,
                ROWS, 3*HD, HD, 1.f, 1, 0,0,0,0,0,0);
        }
        k_rope_split<<<ROWS,256>>>();

        { // S = alpha * Q K^T (causal; masked region zeroed in epilogue)
            dim3 g(17, 17, NZ);
            k_mgemm<0,0,0,0,1,0,2,1><<<g,256,MG_SMEM>>>(
                qh, qh, HDIM, kh, kh, HDIM, nullptr, nullptr,
                nullptr, shh, nullptr, NTOK,
                NTOK, NTOK, HDIM, 0.08838834764831845f,
                NHEADS, (long long)NHEADS*NTOK*HDIM, (long long)NTOK*HDIM,
                        (long long)NHEADS*NTOK*HDIM, (long long)NTOK*HDIM,
                        (long long)NHEADS*SZZ, SZZ);
        }
        { dim3 g(NTOK, NZ); k_softmax<<<g,256>>>(); }
        { // O = S V  (single-product, TRIK; single fp16 out)
            dim3 g(1, 17, NZ);
            k_mgemm<0,0,0,0,0,1,2,1><<<g,256,MG_SMEM>>>(
                shh, shh, NTOK, vth, vth, NTOK, nullptr, nullptr,
                nullptr, aoh, nullptr, HD,
                NTOK, HDIM, NTOK, 1.f,
                NHEADS, (long long)NHEADS*SZZ, SZZ,
                        (long long)NHEADS*HDIM*NTOK, (long long)HDIM*NTOK,
                        (long long)NTOK*HD, (long long)HDIM);
        }
        { // proj + residual -> t  (single-product now)
            dim3 g(HD/128, ROWS/128, 1);
            k_mgemm<1,0,1,0,0,0,0,1><<<g,256,MG_SMEM>>>(
                aoh, aoh, HD, lwph, lwph, HD, pb, t,
                t, nullptr, nullptr, HD,
                ROWS, HD, HD, 1.f, 1, 0,0,0,0,0,0);
        }
        k_ln<<<ROWS,256>>>(ln2_g + l*HD, ln2_b + l*HD, 0);
        { // ff1 + gelu -> hid split  (single-product now)
            dim3 g(4096/128, ROWS/128, 1);
            k_mgemm<1,1,0,0,0,0,1,1><<<g,256,MG_SMEM>>>(
                b1h, b1h, HD, lw1h, lw1h, HD, f1b, nullptr,
                nullptr, hidh, hidl, 4*HD,
                ROWS, 4*HD, HD, 1.f, 1, 0,0,0,0,0,0);
        }
        if (l < LAYERS-1) { // ff2 + residual -> t  (2-product, hid split)
            dim3 g(HD/128, ROWS/128, 1);
            k_mgemm<1,0,1,0,0,0,0,2><<<g,256,MG_SMEM>>>(
                hidh, hidl, 4*HD, lw2h, lw2h, 4*HD, f2b, t,
                t, nullptr, nullptr, HD,
                ROWS, HD, 4*HD, 1.f, 1, 0,0,0,0,0,0);
        } else {            // last layer: fused fp16 convert -> tsh
            dim3 g(HD/128, ROWS/128, 1);
            k_mgemm<1,0,1,0,0,0,2,2><<<g,256,MG_SMEM>>>(
                hidh, hidl, 4*HD, lw2h, lw2h, 4*HD, f2b, t,
                nullptr, tsh, nullptr, HD,
                ROWS, HD, 4*HD, 1.f, 1, 0,0,0,0,0,0);
        }
    }

    // heads: single merged launch, z in {0 = mag, 1 = phase}
    const long long HEAD_ELEMS = (long long)BATCH*16*1024*NTOK;
    {
        dim3 g(16384/128, ROWS/128, 2);
        k_mgemm<1,0,0,1,0,0,0,1><<<g,256,MG_SMEM>>>(
            tsh, tsh, HD, whd, whd, 512, bhd, nullptr,
            out, nullptr, nullptr, 0,
            ROWS, 16384, 512, 1.f,
            1, 512, 0, 16384LL*512, 0, HEAD_ELEMS, 16384);
    }
}

// round 16
// speedup vs baseline: 1.2386x; 1.1172x over previous
#include <cuda_runtime.h>
#include <cuda_fp16.h>
#include <mma.h>
#include <math.h>
#include <stdint.h>

using namespace nvcuda;

#define NTOK   2112
#define BATCH  2
#define HD     1024
#define NHEADS 8
#define HDIM   128
#define LAYERS 8
#define ROWS   (BATCH*NTOK)          // 4224
#define NZ     (BATCH*NHEADS)        // 16
#define SZZ    ((long long)NTOK*NTOK)

// ------------------------- fp32 scratch --------------------------------------
__device__ float g_c1re[BATCH*16*64*33];
__device__ float g_c1im[BATCH*16*64*33];
__device__ float g_tok [BATCH*NTOK*32];
__device__ float g_t   [ROWS*HD];
__device__ float g_buf1[ROWS*HD];
__device__ float g_qkv [ROWS*3*HD];
__device__ float g_bhd [2*16384];            // combined head biases

// ------------------------- fp16 scratch --------------------------------------
__device__ __half g_b1hi [ROWS*HD];
__device__ __half g_qhi  [NZ*NTOK*HDIM];
__device__ __half g_khi  [NZ*NTOK*HDIM];
__device__ __half g_vthi [NZ*HDIM*NTOK];
__device__ __half g_shi  [NZ*NTOK*NTOK];
__device__ __half g_aohi [ROWS*HD];
__device__ __half g_hidhi[ROWS*4*HD];
__device__ __half g_tshi [ROWS*HD];
// weights (single fp16)
__device__ __half g_wqkvhi[LAYERS*3*HD*HD];
__device__ __half g_wprhi [LAYERS*HD*HD];
__device__ __half g_wf1hi [LAYERS*4*HD*HD];
__device__ __half g_wf2hi [LAYERS*4*HD*HD];
__device__ __half g_whd   [2LL*16384*512];   // combined mag+phase head weights

__device__ __forceinline__ float geluf(float v) {
    return 0.5f * v * (1.0f + erff(v * 0.7071067811865476f));
}
__device__ __forceinline__ uint32_t smem_u32(const void* p) {
    uint32_t a;
    asm("{ .reg .u64 t; cvta.to.shared.u64 t, %1; cvt.u32.u64 %0, t; }"
        : "=r"(a) : "l"(p));
    return a;
}
__device__ __forceinline__ void cp16(void* dst, const void* src, int srcBytes) {
    asm volatile("cp.async.cg.shared.global [%0], [%1], 16, %2;"
                 :: "r"(smem_u32(dst)), "l"(src), "r"(srcBytes) : "memory");
}
#define CP_COMMIT() asm volatile("cp.async.commit_group;" ::: "memory")
#define CP_WAIT1()  asm volatile("cp.async.wait_group 1;" ::: "memory")
#define CP_WAIT0()  asm volatile("cp.async.wait_group 0;" ::: "memory")

// ============================ wmma split-fp16 GEMM ===========================
// C = act(alpha * A B^T + bias) [+R]  (NT layout).
// PROD: 3 = AhBh+AhBl+AlBh; 2 = AhBh+AlBh (B single); 1 = AhBh (both single).
// OSPLIT: 0 = fp32 C; 1 = split fp16 Ch+Cl; 2 = single fp16 Ch.
// SCATTER: heads layout; z-batched via sCb (out stride) and sCh2 (bias stride).
// CAUSAL epilogue writes 0 above the diagonal (softmax tail pre-zeroed).
#define MG_SMEM 81920

template<int BIAS, int GELU, int RES, int SCATTER, int CAUSAL, int TRIK,
         int OSPLIT, int PROD>
__global__ __launch_bounds__(256, 2)
void k_mgemm(const __half* __restrict__ Ah_, const __half* __restrict__ Al_,
             long long lda,
             const __half* __restrict__ Bh_, const __half* __restrict__ Bl_,
             long long ldb,
             const float* __restrict__ bias, const float* __restrict__ Rres,
             float* __restrict__ C, __half* __restrict__ Ch,
             __half* __restrict__ Cl, long long ldc,
             int M, int N, int K, float alpha,
             int H, long long sAb, long long sAh2, long long sBb, long long sBh2,
             long long sCb, long long sCh2)
{
    if (CAUSAL && blockIdx.x > blockIdx.y) return;
    int m0 = blockIdx.y*128, n0 = blockIdx.x*128;
    int z = blockIdx.z; int bz = z / H, hz = z - bz*H;
    long long aoff = bz*sAb + hz*sAh2 + (long long)m0*lda;
    long long boff = bz*sBb + hz*sBh2 + (long long)n0*ldb;
    long long coff = bz*sCb + hz*sCh2;
    Ah_ += aoff; Al_ += aoff; Bh_ += boff; Bl_ += boff;
    if (SCATTER) {
        C += bz*sCb;
        if (BIAS) bias += bz*sCh2;
    } else {
        C += coff; if (OSPLIT) { Ch += coff; if (OSPLIT==1) Cl += coff; }
    }

    extern __shared__ char dsm[];
    __half* sbuf  = (__half*)dsm;            // 2 x 20480 halfs (K-loop)
    float*  stage = (float*)dsm;             // 128x128 fp32 (epilogue, aliases)

    int tid = threadIdx.x, wid = tid >> 5;
    int wm = wid & 3, wn = wid >> 2;
    int row2 = tid >> 2, seg = tid & 3;

    int mrows = M - m0; if (mrows > 128) mrows = 128;
    int nrows = N - n0; if (nrows > 128) nrows = 128;
    int Kend = TRIK ? (m0 + 128 < K ? m0 + 128 : K) : K;
    int nch = Kend >> 5;

    wmma::fragment<wmma::accumulator, 16, 16, 16, float> c[2][4];
#pragma unroll
    for (int i = 0; i < 2; i++)
#pragma unroll
        for (int j = 0; j < 4; j++) wmma::fill_fragment(c[i][j], 0.0f);

    const __half* srcs[4] = {Ah_, Al_, Bh_, Bl_};
    long long lds[2] = {lda, ldb};

    auto prefetch = [&](int chunk, int s) {
        long long k0 = (long long)chunk << 5;
        __half* base = sbuf + s*20480;
#pragma unroll
        for (int tno = 0; tno < 4; tno++) {
            if (PROD == 1 && (tno == 1 || tno == 3)) continue;
            if (PROD == 2 && tno == 3) continue;
            int lim = (tno>>1) ? nrows : mrows;
#pragma unroll
            for (int i = 0; i < 2; i++) {
                int r = row2 + 64*i;
                int v2 = (r < lim) ? 16 : 0;
                cp16(base + tno*5120 + r*40 + seg*8,
                     srcs[tno] + (long long)r*lds[tno>>1] + k0 + seg*8, v2);
            }
        }
    };

    prefetch(0, 0);
    CP_COMMIT();

    for (int i = 0; i < nch; i++) {
        if (i + 1 < nch) { prefetch(i+1, (i+1)&1); CP_COMMIT(); CP_WAIT1(); }
        else             { CP_WAIT0(); }
        __syncthreads();
        __half* b = sbuf + (i&1)*20480;
        __half* As_h = b;
        __half* As_l = b + 5120;
        __half* Bs_h = b + 10240;
        __half* Bs_l = b + 15360;
#pragma unroll
        for (int kk = 0; kk < 32; kk += 16) {
            wmma::fragment<wmma::matrix_a, 16, 16, 16, __half, wmma::row_major> fah[2], fal[2];
#pragma unroll
            for (int ii = 0; ii < 2; ii++) {
                wmma::load_matrix_sync(fah[ii], As_h + (wm*32 + ii*16)*40 + kk, 40);
                if (PROD >= 2)
                    wmma::load_matrix_sync(fal[ii], As_l + (wm*32 + ii*16)*40 + kk, 40);
            }
#pragma unroll
            for (int j = 0; j < 4; j++) {
                wmma::fragment<wmma::matrix_b, 16, 16, 16, __half, wmma::col_major> fb;
                wmma::load_matrix_sync(fb, Bs_h + (wn*64 + j*16)*40 + kk, 40);
                wmma::mma_sync(c[0][j], fah[0], fb, c[0][j]);
                wmma::mma_sync(c[1][j], fah[1], fb, c[1][j]);
                if (PROD >= 2) {
                    wmma::mma_sync(c[0][j], fal[0], fb, c[0][j]);
                    wmma::mma_sync(c[1][j], fal[1], fb, c[1][j]);
                }
                if (PROD == 3) {
                    wmma::load_matrix_sync(fb, Bs_l + (wn*64 + j*16)*40 + kk, 40);
                    wmma::mma_sync(c[0][j], fah[0], fb, c[0][j]);
                    wmma::mma_sync(c[1][j], fah[1], fb, c[1][j]);
                }
            }
        }
        __syncthreads();
    }

    // ---- single-pass epilogue: all fragments -> 128x128 fp32 stage ----
#pragma unroll
    for (int ii = 0; ii < 2; ii++)
#pragma unroll
        for (int j = 0; j < 4; j++) {
            if (SCATTER)
                wmma::store_matrix_sync(stage + (wn*64 + j*16)*128 + (wm*32 + ii*16),
                                        c[ii][j], 128, wmma::mem_col_major);
            else
                wmma::store_matrix_sync(stage + (wm*32 + ii*16)*128 + wn*64 + j*16,
                                        c[ii][j], 128, wmma::mem_row_major);
        }
    __syncthreads();
    for (int e = tid; e < 16384; e += 256) {
        int r, col;
        float v;
        if (SCATTER) { r = e & 127; col = e >> 7; v = stage[col*128 + r]; }
        else         { r = e >> 7;  col = e & 127; v = stage[e]; }
        int gm = m0 + r, gn = n0 + col;
        if (gm >= M || gn >= N) continue;
        v *= alpha;
        if (BIAS) v += bias[gn];
        if (GELU) v = geluf(v);
        if (CAUSAL && gn > gm) v = 0.f;   // pre-zero masked region for softmax/SV
        if (SCATTER) {
            int b2 = gm / NTOK;
            int nt = gm - b2*NTOK;
            long long o = ((long long)b2*16384 + (long long)(gn & 15)*1024
                           + (gn >> 4)) * NTOK + nt;
            C[o] = v;
        } else {
            long long o = (long long)gm*ldc + gn;
            if (RES) v += Rres[o];
            if (OSPLIT == 1) {
                __half hh = __float2half(v);
                Ch[o] = hh;
                Cl[o] = __float2half(v - __half2float(hh));
            } else if (OSPLIT == 2) {
                Ch[o] = __float2half(v);
            } else C[o] = v;
        }
    }
}

// ============================ elementwise kernels ============================

// hi-only fp16 convert
__global__ void k_split1(const float* __restrict__ src,
                         __half* __restrict__ hi, long long n) {
    long long i = ((long long)blockIdx.x*256 + threadIdx.x) * 4;
    if (i + 4 <= n) {
        float4 v = *(const float4*)(src + i);
        *(__half2*)(hi + i)     = __halves2half2(__float2half(v.x), __float2half(v.y));
        *(__half2*)(hi + i + 2) = __halves2half2(__float2half(v.z), __float2half(v.w));
    } else {
        for (; i < n; i++) hi[i] = __float2half(src[i]);
    }
}

// fused rope + qkv reorganize; reads fp32 qkv, writes q/k/v single fp16
__global__ void k_rope_split() {
    int row = blockIdx.x;
    int b = row / NTOK, t = row - b*NTOK;
    const float* base = g_qkv + (long long)row*3*HD;
    int tid = threadIdx.x;
    for (int idx = tid; idx < 512; idx += 256) {
        int h = idx >> 6, i = idx & 63;
        float div = expf((float)i * -0.14391156831212787f);
        float ang = (float)t * div;
        float s, c; sincosf(ang, &s, &c);
        int z = b*NHEADS + h;
        long long qi = ((long long)z*NTOK + t)*HDIM + i;
        {
            float q1 = base[h*HDIM + i], q2 = base[h*HDIM + i + 64];
            g_qhi[qi]    = __float2half(q1 + q1*c - q2*s);
            g_qhi[qi+64] = __float2half(q2 + q2*c + q1*s);
        }
        {
            float k1 = base[HD + h*HDIM + i], k2 = base[HD + h*HDIM + i + 64];
            g_khi[qi]    = __float2half(k1 + k1*c - k2*s);
            g_khi[qi+64] = __float2half(k2 + k2*c + k1*s);
        }
    }
    for (int idx = tid; idx < 1024; idx += 256) {
        int h = idx >> 7, d = idx & 127;
        int z = b*NHEADS + h;
        long long vi = ((long long)z*HDIM + d)*NTOK + t;
        g_vthi[vi] = __float2half(base[2*HD + h*HDIM + d]);
    }
}

__global__ void k_dft1(const float* __restrict__ x) {
    int idx = blockIdx.x * 256 + threadIdx.x;
    if (idx >= BATCH*16*64*33) return;
    int v  = idx % 33;
    int t  = idx / 33;
    int y  = t % 64;
    int bc = t / 64;
    const float* xr = x + ((long long)bc*64 + y)*64;
    float re = 0.f, im = 0.f;
    for (int j = 0; j < 64; j++) {
        int m = (v*j) & 63;
        float ang = -0.09817477042468103f * (float)m;
        float s, c; sincosf(ang, &s, &c);
        float xv = xr[j];
        re += xv * c;
        im += xv * s;
    }
    g_c1re[idx] = re;
    g_c1im[idx] = im;
}

__global__ void k_dft2() {
    int idx = blockIdx.x * 256 + threadIdx.x;
    if (idx >= BATCH*16*64*33) return;
    int v  = idx % 33;
    int t  = idx / 33;
    int r  = t % 64;
    int bc = t / 64;
    int b  = bc / 16, c = bc % 16;
    int u  = (r == 0) ? 32 : ((r & 1) ? 32 + ((r+1) >> 1) : 32 - (r >> 1));
    int us = (u + 32) & 63;
    const float* pr = g_c1re + (long long)bc*64*33 + v;
    const float* pi = g_c1im + (long long)bc*64*33 + v;
    float re = 0.f, im = 0.f;
    for (int y = 0; y < 64; y++) {
        int m = (us*y) & 63;
        float ang = -0.09817477042468103f * (float)m;
        float s, cc; sincosf(ang, &s, &cc);
        float ar = pr[y*33], ai = pi[y*33];
        re += ar*cc - ai*s;
        im += ar*s  + ai*cc;
    }
    re *= 0.015625f;
    im *= 0.015625f;
    int n = r*33 + v;
    float* dst = g_tok + ((long long)b*NTOK + n)*32;
    dst[c]      = re;
    dst[16 + c] = im;
}

__global__ void k_shift(const float* __restrict__ cond,
                        const float* __restrict__ dcw,
                        const float* __restrict__ dcb) {
    int idx = blockIdx.x * 256 + threadIdx.x;
    if (idx >= ROWS*HD) return;
    int j = idx & (HD-1);
    int n = (idx >> 10) % NTOK;
    int b = idx / (NTOK*HD);
    if (n == 0) g_t[idx] = cond[b] * dcw[j] + dcb[j];
    else        g_t[idx] = g_buf1[idx - HD];
}

// LayerNorm on g_t -> fp16 hi
__global__ void k_ln(const float* __restrict__ g, const float* __restrict__ b) {
    long long row = blockIdx.x;
    const float* x = g_t + row*HD;
    int tid = threadIdx.x;
    float s = 0.f, q = 0.f;
    for (int j = tid; j < HD; j += 256) { float v = x[j]; s += v; q += v*v; }
    for (int o = 16; o; o >>= 1) {
        s += __shfl_xor_sync(0xffffffffu, s, o);
        q += __shfl_xor_sync(0xffffffffu, q, o);
    }
    __shared__ float shs[8], shq[8];
    if ((tid & 31) == 0) { shs[tid >> 5] = s; shq[tid >> 5] = q; }
    __syncthreads();
    float S = 0.f, Q = 0.f;
    for (int i = 0; i < 8; i++) { S += shs[i]; Q += shq[i]; }
    float mean = S * (1.0f/HD);
    float var  = Q * (1.0f/HD) - mean*mean;
    float rstd = rsqrtf(var + 1e-5f);
    for (int j = tid; j < HD; j += 256) {
        float v = (x[j] - mean) * rstd * g[j] + b[j];
        g_b1hi[row*HD + j] = __float2half(v);
    }
}

// causal softmax on single-fp16 S (in place) — tail already zeroed by QK GEMM
__global__ void k_softmax() {
    int q = blockIdx.x, z = blockIdx.y;
    __half* oh = g_shi + ((long long)z*NTOK + q)*NTOK;
    int len = q + 1;
    int tid = threadIdx.x;
    float vals[9];
    int cnt = 0;
    float m = -3.4e38f;
    for (int k = tid; k < len; k += 256) {
        float v = __half2float(oh[k]);
        vals[cnt++] = v;
        m = fmaxf(m, v);
    }
    __shared__ float sh[16];
    for (int o = 16; o; o >>= 1) m = fmaxf(m, __shfl_xor_sync(0xffffffffu, m, o));
    if ((tid & 31) == 0) sh[tid >> 5] = m;
    __syncthreads();
    float M = sh[0];
    for (int i = 1; i < 8; i++) M = fmaxf(M, sh[i]);
    float s = 0.f;
    for (int i = 0; i < cnt; i++) {
        vals[i] = __expf(vals[i] - M);
        s += vals[i];
    }
    for (int o = 16; o; o >>= 1) s += __shfl_xor_sync(0xffffffffu, s, o);
    if ((tid & 31) == 0) sh[8 + (tid >> 5)] = s;
    __syncthreads();
    float T = 0.f;
    for (int i = 0; i < 8; i++) T += sh[8+i];
    float inv = 1.0f / T;
    cnt = 0;
    for (int k = tid; k < len; k += 256)
        oh[k] = __float2half(vals[cnt++] * inv);
}

// ------------------- fp32 SGEMM (init linear only, K=32) --------------------
__global__ __launch_bounds__(256)
void k_gemm32(const float* __restrict__ A, const float* __restrict__ B,
              const float* __restrict__ bias, float* __restrict__ C,
              int M, int N, int K, int lda, int ldb, int ldc)
{
    int m0 = blockIdx.y * 128, n0 = blockIdx.x * 128;
    __shared__ __align__(16) float As[8][128];
    __shared__ __align__(16) float Bs[8][128];
    float acc[8][8];
#pragma unroll
    for (int i = 0; i < 8; i++)
#pragma unroll
        for (int j = 0; j < 8; j++) acc[i][j] = 0.f;
    int tid  = threadIdx.x;
    int arow = tid >> 1,  ak = (tid & 1) << 2;
    int ty   = tid >> 4,  tx = tid & 15;
    const float* Aload = A + (long long)(m0 + arow)*lda + ak;
    bool aValid = (m0 + arow) < M;
    const float* Bload = B + (long long)(n0 + arow)*ldb + ak;
    bool bValid = (n0 + arow) < N;
    for (int k0 = 0; k0 < K; k0 += 8) {
        float4 av = aValid ? *(const float4*)(Aload + k0) : make_float4(0,0,0,0);
        As[ak+0][arow] = av.x; As[ak+1][arow] = av.y;
        As[ak+2][arow] = av.z; As[ak+3][arow] = av.w;
        float4 bv = bValid ? *(const float4*)(Bload + k0) : make_float4(0,0,0,0);
        Bs[ak+0][arow] = bv.x; Bs[ak+1][arow] = bv.y;
        Bs[ak+2][arow] = bv.z; Bs[ak+3][arow] = bv.w;
        __syncthreads();
#pragma unroll
        for (int kk = 0; kk < 8; kk++) {
            float a[8], b[8];
            *(float4*)(a)   = *(const float4*)&As[kk][ty*8];
            *(float4*)(a+4) = *(const float4*)&As[kk][ty*8+4];
            *(float4*)(b)   = *(const float4*)&Bs[kk][tx*8];
            *(float4*)(b+4) = *(const float4*)&Bs[kk][tx*8+4];
#pragma unroll
            for (int mi = 0; mi < 8; mi++)
#pragma unroll
                for (int ni = 0; ni < 8; ni++)
                    acc[mi][ni] += a[mi] * b[ni];
        }
        __syncthreads();
    }
#pragma unroll
    for (int mi = 0; mi < 8; mi++) {
        int gm = m0 + ty*8 + mi;
        if (gm >= M) continue;
#pragma unroll
        for (int ni = 0; ni < 8; ni++) {
            int gn = n0 + tx*8 + ni;
            if (gn >= N) continue;
            C[(long long)gm*ldc + gn] = acc[mi][ni] + bias[gn];
        }
    }
}

// ----------------------------------- host -----------------------------------
extern "C" void kernel_launch(void* const* d_in, const int* in_sizes, int n_in,
                              void* d_out, int out_size) {
    const float* x      = (const float*)d_in[0];
    const float* cond   = (const float*)d_in[1];
    const float* init_w = (const float*)d_in[2];
    const float* init_b = (const float*)d_in[3];
    const float* dc_w   = (const float*)d_in[4];
    const float* dc_b   = (const float*)d_in[5];
    const float* ln1_g  = (const float*)d_in[6];
    const float* ln1_b  = (const float*)d_in[7];
    const float* qkv_w  = (const float*)d_in[8];
    const float* qkv_b  = (const float*)d_in[9];
    const float* proj_w = (const float*)d_in[10];
    const float* proj_b = (const float*)d_in[11];
    const float* ln2_g  = (const float*)d_in[12];
    const float* ln2_b  = (const float*)d_in[13];
    const float* ff1_w  = (const float*)d_in[14];
    const float* ff1_b  = (const float*)d_in[15];
    const float* ff2_w  = (const float*)d_in[16];
    const float* ff2_b  = (const float*)d_in[17];
    const float* mag_w  = (const float*)d_in[18];
    const float* mag_b  = (const float*)d_in[19];
    const float* ph_w   = (const float*)d_in[20];
    const float* ph_b   = (const float*)d_in[21];
    float* out = (float*)d_out;

    float *tok, *t, *buf1, *qkv, *bhd;
    cudaGetSymbolAddress((void**)&tok,  g_tok);
    cudaGetSymbolAddress((void**)&t,    g_t);
    cudaGetSymbolAddress((void**)&buf1, g_buf1);
    cudaGetSymbolAddress((void**)&qkv,  g_qkv);
    cudaGetSymbolAddress((void**)&bhd,  g_bhd);
    __half *b1h,*qh,*kh,*vth,*shh,*aoh,*hidh,*tsh,
           *wqh,*wph2,*wf1h,*wf2h,*whd;
    cudaGetSymbolAddress((void**)&b1h,  g_b1hi);
    cudaGetSymbolAddress((void**)&qh,   g_qhi);
    cudaGetSymbolAddress((void**)&kh,   g_khi);
    cudaGetSymbolAddress((void**)&vth,  g_vthi);
    cudaGetSymbolAddress((void**)&shh,  g_shi);
    cudaGetSymbolAddress((void**)&aoh,  g_aohi);
    cudaGetSymbolAddress((void**)&hidh, g_hidhi);
    cudaGetSymbolAddress((void**)&tsh,  g_tshi);
    cudaGetSymbolAddress((void**)&wqh,  g_wqkvhi);
    cudaGetSymbolAddress((void**)&wph2, g_wprhi);
    cudaGetSymbolAddress((void**)&wf1h, g_wf1hi);
    cudaGetSymbolAddress((void**)&wf2h, g_wf2hi);
    cudaGetSymbolAddress((void**)&whd,  g_whd);

    cudaFuncSetAttribute(k_mgemm<1,0,0,0,0,0,0,1>, cudaFuncAttributeMaxDynamicSharedMemorySize, MG_SMEM);
    cudaFuncSetAttribute(k_mgemm<0,0,0,0,1,0,2,1>, cudaFuncAttributeMaxDynamicSharedMemorySize, MG_SMEM);
    cudaFuncSetAttribute(k_mgemm<0,0,0,0,0,1,2,1>, cudaFuncAttributeMaxDynamicSharedMemorySize, MG_SMEM);
    cudaFuncSetAttribute(k_mgemm<1,0,1,0,0,0,0,1>, cudaFuncAttributeMaxDynamicSharedMemorySize, MG_SMEM);
    cudaFuncSetAttribute(k_mgemm<1,1,0,0,0,0,2,1>, cudaFuncAttributeMaxDynamicSharedMemorySize, MG_SMEM);
    cudaFuncSetAttribute(k_mgemm<1,0,1,0,0,0,2,1>, cudaFuncAttributeMaxDynamicSharedMemorySize, MG_SMEM);
    cudaFuncSetAttribute(k_mgemm<1,0,0,1,0,0,0,1>, cudaFuncAttributeMaxDynamicSharedMemorySize, MG_SMEM);

    // ---- convert all weights to single fp16; gather head biases ----
    {
        long long n;
        n = (long long)LAYERS*3*HD*HD; k_split1<<<(int)((n/4+255)/256),256>>>(qkv_w,  wqh,  n);
        n = (long long)LAYERS*HD*HD;   k_split1<<<(int)((n/4+255)/256),256>>>(proj_w, wph2, n);
        n = (long long)LAYERS*4*HD*HD; k_split1<<<(int)((n/4+255)/256),256>>>(ff1_w,  wf1h, n);
        n = (long long)LAYERS*4*HD*HD; k_split1<<<(int)((n/4+255)/256),256>>>(ff2_w,  wf2h, n);
        n = (long long)16384*512;      k_split1<<<(int)((n/4+255)/256),256>>>(mag_w,  whd,  n);
        n = (long long)16384*512;      k_split1<<<(int)((n/4+255)/256),256>>>(ph_w,   whd + 16384LL*512, n);
        cudaMemcpyAsync(bhd,         mag_b, 16384*sizeof(float), cudaMemcpyDeviceToDevice);
        cudaMemcpyAsync(bhd + 16384, ph_b,  16384*sizeof(float), cudaMemcpyDeviceToDevice);
    }

    // ---- FFT + token build + init linear + shift ----
    int nfft = BATCH*16*64*33;
    k_dft1<<<(nfft+255)/256, 256>>>(x);
    k_dft2<<<(nfft+255)/256, 256>>>();
    {
        dim3 g(1024/128, ROWS/128);
        k_gemm32<<<g,256>>>(tok, init_w, init_b, buf1, ROWS, 1024, 32, 32, 32, 1024);
    }
    k_shift<<<(ROWS*HD+255)/256, 256>>>(cond, dc_w, dc_b);

    for (int l = 0; l < LAYERS; l++) {
        const float* qb  = qkv_b + l*3*HD;
        const float* pb  = proj_b + l*HD;
        const float* f1b = ff1_b + l*4*HD;
        const float* f2b = ff2_b + l*HD;
        const __half* lwqh = wqh  + (long long)l*3*HD*HD;
        const __half* lwph = wph2 + (long long)l*HD*HD;
        const __half* lw1h = wf1h + (long long)l*4*HD*HD;
        const __half* lw2h = wf2h + (long long)l*4*HD*HD;

        k_ln<<<ROWS,256>>>(ln1_g + l*HD, ln1_b + l*HD);

        { // qkv (single-product, fp32 out)
            dim3 g(3072/128, ROWS/128, 1);
            k_mgemm<1,0,0,0,0,0,0,1><<<g,256,MG_SMEM>>>(
                b1h, b1h, HD, lwqh, lwqh, HD, qb, nullptr,
                qkv, nullptr, nullptr, 3*HD,
                ROWS, 3*HD, HD, 1.f, 1, 0,0,0,0,0,0);
        }
        k_rope_split<<<ROWS,256>>>();

        { // S = alpha * Q K^T (causal; masked region zeroed in epilogue)
            dim3 g(17, 17, NZ);
            k_mgemm<0,0,0,0,1,0,2,1><<<g,256,MG_SMEM>>>(
                qh, qh, HDIM, kh, kh, HDIM, nullptr, nullptr,
                nullptr, shh, nullptr, NTOK,
                NTOK, NTOK, HDIM, 0.08838834764831845f,
                NHEADS, (long long)NHEADS*NTOK*HDIM, (long long)NTOK*HDIM,
                        (long long)NHEADS*NTOK*HDIM, (long long)NTOK*HDIM,
                        (long long)NHEADS*SZZ, SZZ);
        }
        { dim3 g(NTOK, NZ); k_softmax<<<g,256>>>(); }
        { // O = S V  (single-product, TRIK; single fp16 out)
            dim3 g(1, 17, NZ);
            k_mgemm<0,0,0,0,0,1,2,1><<<g,256,MG_SMEM>>>(
                shh, shh, NTOK, vth, vth, NTOK, nullptr, nullptr,
                nullptr, aoh, nullptr, HD,
                NTOK, HDIM, NTOK, 1.f,
                NHEADS, (long long)NHEADS*SZZ, SZZ,
                        (long long)NHEADS*HDIM*NTOK, (long long)HDIM*NTOK,
                        (long long)NTOK*HD, (long long)HDIM);
        }
        { // proj + residual -> t  (single-product)
            dim3 g(HD/128, ROWS/128, 1);
            k_mgemm<1,0,1,0,0,0,0,1><<<g,256,MG_SMEM>>>(
                aoh, aoh, HD, lwph, lwph, HD, pb, t,
                t, nullptr, nullptr, HD,
                ROWS, HD, HD, 1.f, 1, 0,0,0,0,0,0);
        }
        k_ln<<<ROWS,256>>>(ln2_g + l*HD, ln2_b + l*HD);
        { // ff1 + gelu -> hid single fp16 (single-product)
            dim3 g(4096/128, ROWS/128, 1);
            k_mgemm<1,1,0,0,0,0,2,1><<<g,256,MG_SMEM>>>(
                b1h, b1h, HD, lw1h, lw1h, HD, f1b, nullptr,
                nullptr, hidh, nullptr, 4*HD,
                ROWS, 4*HD, HD, 1.f, 1, 0,0,0,0,0,0);
        }
        if (l < LAYERS-1) { // ff2 + residual -> t  (single-product now)
            dim3 g(HD/128, ROWS/128, 1);
            k_mgemm<1,0,1,0,0,0,0,1><<<g,256,MG_SMEM>>>(
                hidh, hidh, 4*HD, lw2h, lw2h, 4*HD, f2b, t,
                t, nullptr, nullptr, HD,
                ROWS, HD, 4*HD, 1.f, 1, 0,0,0,0,0,0);
        } else {            // last layer: fused fp16 convert -> tsh
            dim3 g(HD/128, ROWS/128, 1);
            k_mgemm<1,0,1,0,0,0,2,1><<<g,256,MG_SMEM>>>(
                hidh, hidh, 4*HD, lw2h, lw2h, 4*HD, f2b, t,
                nullptr, tsh, nullptr, HD,
                ROWS, HD, 4*HD, 1.f, 1, 0,0,0,0,0,0);
        }
    }

    // heads: single merged launch, z in {0 = mag, 1 = phase}
    const long long HEAD_ELEMS = (long long)BATCH*16*1024*NTOK;
    {
        dim3 g(16384/128, ROWS/128, 2);
        k_mgemm<1,0,0,1,0,0,0,1><<<g,256,MG_SMEM>>>(
            tsh, tsh, HD, whd, whd, 512, bhd, nullptr,
            out, nullptr, nullptr, 0,
            ROWS, 16384, 512, 1.f,
            1, 512, 0, 16384LL*512, 0, HEAD_ELEMS, 16384);
    }
}

// round 17
// speedup vs baseline: 1.2794x; 1.0329x over previous
#include <cuda_runtime.h>
#include <cuda_fp16.h>
#include <mma.h>
#include <math.h>
#include <stdint.h>

using namespace nvcuda;

#define NTOK   2112
#define BATCH  2
#define HD     1024
#define NHEADS 8
#define HDIM   128
#define LAYERS 8
#define ROWS   (BATCH*NTOK)          // 4224
#define NZ     (BATCH*NHEADS)        // 16
#define SZZ    ((long long)NTOK*NTOK)

// ------------------------- fp32 scratch --------------------------------------
__device__ float g_c1re[BATCH*16*64*33];
__device__ float g_c1im[BATCH*16*64*33];
__device__ float g_tok [BATCH*NTOK*32];
__device__ float g_t   [ROWS*HD];
__device__ float g_buf1[ROWS*HD];
__device__ float g_bhd [2*16384];            // combined head biases

// ------------------------- fp16 scratch --------------------------------------
__device__ __half g_b1hi [ROWS*HD];
__device__ __half g_qhi  [NZ*NTOK*HDIM];
__device__ __half g_khi  [NZ*NTOK*HDIM];
__device__ __half g_vthi [NZ*HDIM*NTOK];
__device__ __half g_shi  [NZ*NTOK*NTOK];
__device__ __half g_aohi [ROWS*HD];
__device__ __half g_hidhi[ROWS*4*HD];
__device__ __half g_tshi [ROWS*HD];
// weights (single fp16)
__device__ __half g_wqkvhi[LAYERS*3*HD*HD];
__device__ __half g_wprhi [LAYERS*HD*HD];
__device__ __half g_wf1hi [LAYERS*4*HD*HD];
__device__ __half g_wf2hi [LAYERS*4*HD*HD];
__device__ __half g_whd   [2LL*16384*512];   // combined mag+phase head weights

__device__ __forceinline__ float geluf(float v) {
    return 0.5f * v * (1.0f + erff(v * 0.7071067811865476f));
}
__device__ __forceinline__ uint32_t smem_u32(const void* p) {
    uint32_t a;
    asm("{ .reg .u64 t; cvta.to.shared.u64 t, %1; cvt.u32.u64 %0, t; }"
        : "=r"(a) : "l"(p));
    return a;
}
__device__ __forceinline__ void cp16(void* dst, const void* src, int srcBytes) {
    asm volatile("cp.async.cg.shared.global [%0], [%1], 16, %2;"
                 :: "r"(smem_u32(dst)), "l"(src), "r"(srcBytes) : "memory");
}
#define CP_COMMIT() asm volatile("cp.async.commit_group;" ::: "memory")
#define CP_WAIT1()  asm volatile("cp.async.wait_group 1;" ::: "memory")
#define CP_WAIT0()  asm volatile("cp.async.wait_group 0;" ::: "memory")

// ============================ wmma split-fp16 GEMM ===========================
// C = act(alpha * A B^T + bias) [+R]  (NT layout).
// PROD: 3 = AhBh+AhBl+AlBh; 2 = AhBh+AlBh (B single); 1 = AhBh (both single).
// OSPLIT: 0 = fp32 C; 1 = split fp16 Ch+Cl; 2 = single fp16 Ch.
// SCATTER: heads layout; z-batched via sCb (out stride) and sCh2 (bias stride).
// CAUSAL epilogue writes 0 above the diagonal (softmax tail pre-zeroed).
// ROPE: qkv epilogue — applies RoPE to q/k sections and writes q/k (token-major)
//       and v (dim-major transposed) fp16 directly; C pointers unused.
#define MG_SMEM 81920

template<int BIAS, int GELU, int RES, int SCATTER, int CAUSAL, int TRIK,
         int OSPLIT, int PROD, int ROPE>
__global__ __launch_bounds__(256, 2)
void k_mgemm(const __half* __restrict__ Ah_, const __half* __restrict__ Al_,
             long long lda,
             const __half* __restrict__ Bh_, const __half* __restrict__ Bl_,
             long long ldb,
             const float* __restrict__ bias, const float* __restrict__ Rres,
             float* __restrict__ C, __half* __restrict__ Ch,
             __half* __restrict__ Cl, long long ldc,
             int M, int N, int K, float alpha,
             int H, long long sAb, long long sAh2, long long sBb, long long sBh2,
             long long sCb, long long sCh2)
{
    if (CAUSAL && blockIdx.x > blockIdx.y) return;
    int m0 = blockIdx.y*128, n0 = blockIdx.x*128;
    int z = blockIdx.z; int bz = z / H, hz = z - bz*H;
    long long aoff = bz*sAb + hz*sAh2 + (long long)m0*lda;
    long long boff = bz*sBb + hz*sBh2 + (long long)n0*ldb;
    long long coff = bz*sCb + hz*sCh2;
    Ah_ += aoff; Al_ += aoff; Bh_ += boff; Bl_ += boff;
    if (SCATTER) {
        C += bz*sCb;
        if (BIAS) bias += bz*sCh2;
    } else if (!ROPE) {
        C += coff; if (OSPLIT) { Ch += coff; if (OSPLIT==1) Cl += coff; }
    }

    extern __shared__ char dsm[];
    __half* sbuf  = (__half*)dsm;            // 2 x 20480 halfs (K-loop)
    float*  stage = (float*)dsm;             // 128x128 fp32 (epilogue, aliases)

    int tid = threadIdx.x, wid = tid >> 5;
    int wm = wid & 3, wn = wid >> 2;
    int row2 = tid >> 2, seg = tid & 3;

    int mrows = M - m0; if (mrows > 128) mrows = 128;
    int nrows = N - n0; if (nrows > 128) nrows = 128;
    int Kend = TRIK ? (m0 + 128 < K ? m0 + 128 : K) : K;
    int nch = Kend >> 5;

    wmma::fragment<wmma::accumulator, 16, 16, 16, float> c[2][4];
#pragma unroll
    for (int i = 0; i < 2; i++)
#pragma unroll
        for (int j = 0; j < 4; j++) wmma::fill_fragment(c[i][j], 0.0f);

    const __half* srcs[4] = {Ah_, Al_, Bh_, Bl_};
    long long lds[2] = {lda, ldb};

    auto prefetch = [&](int chunk, int s) {
        long long k0 = (long long)chunk << 5;
        __half* base = sbuf + s*20480;
#pragma unroll
        for (int tno = 0; tno < 4; tno++) {
            if (PROD == 1 && (tno == 1 || tno == 3)) continue;
            if (PROD == 2 && tno == 3) continue;
            int lim = (tno>>1) ? nrows : mrows;
#pragma unroll
            for (int i = 0; i < 2; i++) {
                int r = row2 + 64*i;
                int v2 = (r < lim) ? 16 : 0;
                cp16(base + tno*5120 + r*40 + seg*8,
                     srcs[tno] + (long long)r*lds[tno>>1] + k0 + seg*8, v2);
            }
        }
    };

    prefetch(0, 0);
    CP_COMMIT();

    for (int i = 0; i < nch; i++) {
        if (i + 1 < nch) { prefetch(i+1, (i+1)&1); CP_COMMIT(); CP_WAIT1(); }
        else             { CP_WAIT0(); }
        __syncthreads();
        __half* b = sbuf + (i&1)*20480;
        __half* As_h = b;
        __half* As_l = b + 5120;
        __half* Bs_h = b + 10240;
        __half* Bs_l = b + 15360;
#pragma unroll
        for (int kk = 0; kk < 32; kk += 16) {
            wmma::fragment<wmma::matrix_a, 16, 16, 16, __half, wmma::row_major> fah[2], fal[2];
#pragma unroll
            for (int ii = 0; ii < 2; ii++) {
                wmma::load_matrix_sync(fah[ii], As_h + (wm*32 + ii*16)*40 + kk, 40);
                if (PROD >= 2)
                    wmma::load_matrix_sync(fal[ii], As_l + (wm*32 + ii*16)*40 + kk, 40);
            }
#pragma unroll
            for (int j = 0; j < 4; j++) {
                wmma::fragment<wmma::matrix_b, 16, 16, 16, __half, wmma::col_major> fb;
                wmma::load_matrix_sync(fb, Bs_h + (wn*64 + j*16)*40 + kk, 40);
                wmma::mma_sync(c[0][j], fah[0], fb, c[0][j]);
                wmma::mma_sync(c[1][j], fah[1], fb, c[1][j]);
                if (PROD >= 2) {
                    wmma::mma_sync(c[0][j], fal[0], fb, c[0][j]);
                    wmma::mma_sync(c[1][j], fal[1], fb, c[1][j]);
                }
                if (PROD == 3) {
                    wmma::load_matrix_sync(fb, Bs_l + (wn*64 + j*16)*40 + kk, 40);
                    wmma::mma_sync(c[0][j], fah[0], fb, c[0][j]);
                    wmma::mma_sync(c[1][j], fah[1], fb, c[1][j]);
                }
            }
        }
        __syncthreads();
    }

    // section for ROPE epilogue: 0=q, 1=k, 2=v (uniform per CTA)
    int sec = ROPE ? (n0 >> 10) : 0;
    int hh2 = ROPE ? ((n0 & 1023) >> 7) : 0;
    // col-major stage for SCATTER (token-fastest) and ROPE v-transpose
    bool cmaj = SCATTER || (ROPE && sec == 2);

    // ---- single-pass epilogue: all fragments -> 128x128 fp32 stage ----
#pragma unroll
    for (int ii = 0; ii < 2; ii++)
#pragma unroll
        for (int j = 0; j < 4; j++) {
            if (cmaj)
                wmma::store_matrix_sync(stage + (wn*64 + j*16)*128 + (wm*32 + ii*16),
                                        c[ii][j], 128, wmma::mem_col_major);
            else
                wmma::store_matrix_sync(stage + (wm*32 + ii*16)*128 + wn*64 + j*16,
                                        c[ii][j], 128, wmma::mem_row_major);
        }
    __syncthreads();

    if (ROPE) {
        if (sec < 2) {
            // q/k: row-major stage; consecutive threads walk d -> coalesced
            for (int e = tid; e < 16384; e += 256) {
                int r = e >> 7, col = e & 127;
                int gm = m0 + r;
                int b2 = gm / NTOK, t = gm - b2*NTOK;
                float vme = stage[r*128 + col]        + bias[n0 + col];
                float vp  = stage[r*128 + (col^64)]   + bias[n0 + (col^64)];
                int i = col & 63;
                float div = expf((float)i * -0.14391156831212787f);
                float ang = (float)t * div;
                float s, cc; sincosf(ang, &s, &cc);
                float outv = (col < 64) ? (vme + vme*cc - vp*s)
                                        : (vme + vme*cc + vp*s);
                long long qi = ((long long)(b2*NHEADS + hh2)*NTOK + t)*HDIM + col;
                if (sec == 0) g_qhi[qi] = __float2half(outv);
                else          g_khi[qi] = __float2half(outv);
            }
        } else {
            // v: col-major stage; consecutive threads walk t -> coalesced
            for (int e = tid; e < 16384; e += 256) {
                int r = e & 127, col = e >> 7;
                int gm = m0 + r;
                int b2 = gm / NTOK, t = gm - b2*NTOK;
                float v = stage[col*128 + r] + bias[n0 + col];
                long long vi = ((long long)(b2*NHEADS + hh2)*HDIM + col)*NTOK + t;
                g_vthi[vi] = __float2half(v);
            }
        }
        return;
    }

    for (int e = tid; e < 16384; e += 256) {
        int r, col;
        float v;
        if (SCATTER) { r = e & 127; col = e >> 7; v = stage[col*128 + r]; }
        else         { r = e >> 7;  col = e & 127; v = stage[e]; }
        int gm = m0 + r, gn = n0 + col;
        if (gm >= M || gn >= N) continue;
        v *= alpha;
        if (BIAS) v += bias[gn];
        if (GELU) v = geluf(v);
        if (CAUSAL && gn > gm) v = 0.f;   // pre-zero masked region for softmax/SV
        if (SCATTER) {
            int b2 = gm / NTOK;
            int nt = gm - b2*NTOK;
            long long o = ((long long)b2*16384 + (long long)(gn & 15)*1024
                           + (gn >> 4)) * NTOK + nt;
            C[o] = v;
        } else {
            long long o = (long long)gm*ldc + gn;
            if (RES) v += Rres[o];
            if (OSPLIT == 1) {
                __half hh = __float2half(v);
                Ch[o] = hh;
                Cl[o] = __float2half(v - __half2float(hh));
            } else if (OSPLIT == 2) {
                Ch[o] = __float2half(v);
            } else C[o] = v;
        }
    }
}

// ============================ elementwise kernels ============================

// hi-only fp16 convert
__global__ void k_split1(const float* __restrict__ src,
                         __half* __restrict__ hi, long long n) {
    long long i = ((long long)blockIdx.x*256 + threadIdx.x) * 4;
    if (i + 4 <= n) {
        float4 v = *(const float4*)(src + i);
        *(__half2*)(hi + i)     = __halves2half2(__float2half(v.x), __float2half(v.y));
        *(__half2*)(hi + i + 2) = __halves2half2(__float2half(v.z), __float2half(v.w));
    } else {
        for (; i < n; i++) hi[i] = __float2half(src[i]);
    }
}

__global__ void k_dft1(const float* __restrict__ x) {
    int idx = blockIdx.x * 256 + threadIdx.x;
    if (idx >= BATCH*16*64*33) return;
    int v  = idx % 33;
    int t  = idx / 33;
    int y  = t % 64;
    int bc = t / 64;
    const float* xr = x + ((long long)bc*64 + y)*64;
    float re = 0.f, im = 0.f;
    for (int j = 0; j < 64; j++) {
        int m = (v*j) & 63;
        float ang = -0.09817477042468103f * (float)m;
        float s, c; sincosf(ang, &s, &c);
        float xv = xr[j];
        re += xv * c;
        im += xv * s;
    }
    g_c1re[idx] = re;
    g_c1im[idx] = im;
}

__global__ void k_dft2() {
    int idx = blockIdx.x * 256 + threadIdx.x;
    if (idx >= BATCH*16*64*33) return;
    int v  = idx % 33;
    int t  = idx / 33;
    int r  = t % 64;
    int bc = t / 64;
    int b  = bc / 16, c = bc % 16;
    int u  = (r == 0) ? 32 : ((r & 1) ? 32 + ((r+1) >> 1) : 32 - (r >> 1));
    int us = (u + 32) & 63;
    const float* pr = g_c1re + (long long)bc*64*33 + v;
    const float* pi = g_c1im + (long long)bc*64*33 + v;
    float re = 0.f, im = 0.f;
    for (int y = 0; y < 64; y++) {
        int m = (us*y) & 63;
        float ang = -0.09817477042468103f * (float)m;
        float s, cc; sincosf(ang, &s, &cc);
        float ar = pr[y*33], ai = pi[y*33];
        re += ar*cc - ai*s;
        im += ar*s  + ai*cc;
    }
    re *= 0.015625f;
    im *= 0.015625f;
    int n = r*33 + v;
    float* dst = g_tok + ((long long)b*NTOK + n)*32;
    dst[c]      = re;
    dst[16 + c] = im;
}

__global__ void k_shift(const float* __restrict__ cond,
                        const float* __restrict__ dcw,
                        const float* __restrict__ dcb) {
    int idx = blockIdx.x * 256 + threadIdx.x;
    if (idx >= ROWS*HD) return;
    int j = idx & (HD-1);
    int n = (idx >> 10) % NTOK;
    int b = idx / (NTOK*HD);
    if (n == 0) g_t[idx] = cond[b] * dcw[j] + dcb[j];
    else        g_t[idx] = g_buf1[idx - HD];
}

// LayerNorm on g_t -> fp16 hi
__global__ void k_ln(const float* __restrict__ g, const float* __restrict__ b) {
    long long row = blockIdx.x;
    const float* x = g_t + row*HD;
    int tid = threadIdx.x;
    float s = 0.f, q = 0.f;
    for (int j = tid; j < HD; j += 256) { float v = x[j]; s += v; q += v*v; }
    for (int o = 16; o; o >>= 1) {
        s += __shfl_xor_sync(0xffffffffu, s, o);
        q += __shfl_xor_sync(0xffffffffu, q, o);
    }
    __shared__ float shs[8], shq[8];
    if ((tid & 31) == 0) { shs[tid >> 5] = s; shq[tid >> 5] = q; }
    __syncthreads();
    float S = 0.f, Q = 0.f;
    for (int i = 0; i < 8; i++) { S += shs[i]; Q += shq[i]; }
    float mean = S * (1.0f/HD);
    float var  = Q * (1.0f/HD) - mean*mean;
    float rstd = rsqrtf(var + 1e-5f);
    for (int j = tid; j < HD; j += 256) {
        float v = (x[j] - mean) * rstd * g[j] + b[j];
        g_b1hi[row*HD + j] = __float2half(v);
    }
}

// causal softmax on single-fp16 S (in place) — tail already zeroed by QK GEMM
__global__ void k_softmax() {
    int q = blockIdx.x, z = blockIdx.y;
    __half* oh = g_shi + ((long long)z*NTOK + q)*NTOK;
    int len = q + 1;
    int tid = threadIdx.x;
    float vals[9];
    int cnt = 0;
    float m = -3.4e38f;
    for (int k = tid; k < len; k += 256) {
        float v = __half2float(oh[k]);
        vals[cnt++] = v;
        m = fmaxf(m, v);
    }
    __shared__ float sh[16];
    for (int o = 16; o; o >>= 1) m = fmaxf(m, __shfl_xor_sync(0xffffffffu, m, o));
    if ((tid & 31) == 0) sh[tid >> 5] = m;
    __syncthreads();
    float M = sh[0];
    for (int i = 1; i < 8; i++) M = fmaxf(M, sh[i]);
    float s = 0.f;
    for (int i = 0; i < cnt; i++) {
        vals[i] = __expf(vals[i] - M);
        s += vals[i];
    }
    for (int o = 16; o; o >>= 1) s += __shfl_xor_sync(0xffffffffu, s, o);
    if ((tid & 31) == 0) sh[8 + (tid >> 5)] = s;
    __syncthreads();
    float T = 0.f;
    for (int i = 0; i < 8; i++) T += sh[8+i];
    float inv = 1.0f / T;
    cnt = 0;
    for (int k = tid; k < len; k += 256)
        oh[k] = __float2half(vals[cnt++] * inv);
}

// ------------------- fp32 SGEMM (init linear only, K=32) --------------------
__global__ __launch_bounds__(256)
void k_gemm32(const float* __restrict__ A, const float* __restrict__ B,
              const float* __restrict__ bias, float* __restrict__ C,
              int M, int N, int K, int lda, int ldb, int ldc)
{
    int m0 = blockIdx.y * 128, n0 = blockIdx.x * 128;
    __shared__ __align__(16) float As[8][128];
    __shared__ __align__(16) float Bs[8][128];
    float acc[8][8];
#pragma unroll
    for (int i = 0; i < 8; i++)
#pragma unroll
        for (int j = 0; j < 8; j++) acc[i][j] = 0.f;
    int tid  = threadIdx.x;
    int arow = tid >> 1,  ak = (tid & 1) << 2;
    int ty   = tid >> 4,  tx = tid & 15;
    const float* Aload = A + (long long)(m0 + arow)*lda + ak;
    bool aValid = (m0 + arow) < M;
    const float* Bload = B + (long long)(n0 + arow)*ldb + ak;
    bool bValid = (n0 + arow) < N;
    for (int k0 = 0; k0 < K; k0 += 8) {
        float4 av = aValid ? *(const float4*)(Aload + k0) : make_float4(0,0,0,0);
        As[ak+0][arow] = av.x; As[ak+1][arow] = av.y;
        As[ak+2][arow] = av.z; As[ak+3][arow] = av.w;
        float4 bv = bValid ? *(const float4*)(Bload + k0) : make_float4(0,0,0,0);
        Bs[ak+0][arow] = bv.x; Bs[ak+1][arow] = bv.y;
        Bs[ak+2][arow] = bv.z; Bs[ak+3][arow] = bv.w;
        __syncthreads();
#pragma unroll
        for (int kk = 0; kk < 8; kk++) {
            float a[8], b[8];
            *(float4*)(a)   = *(const float4*)&As[kk][ty*8];
            *(float4*)(a+4) = *(const float4*)&As[kk][ty*8+4];
            *(float4*)(b)   = *(const float4*)&Bs[kk][tx*8];
            *(float4*)(b+4) = *(const float4*)&Bs[kk][tx*8+4];
#pragma unroll
            for (int mi = 0; mi < 8; mi++)
#pragma unroll
                for (int ni = 0; ni < 8; ni++)
                    acc[mi][ni] += a[mi] * b[ni];
        }
        __syncthreads();
    }
#pragma unroll
    for (int mi = 0; mi < 8; mi++) {
        int gm = m0 + ty*8 + mi;
        if (gm >= M) continue;
#pragma unroll
        for (int ni = 0; ni < 8; ni++) {
            int gn = n0 + tx*8 + ni;
            if (gn >= N) continue;
            C[(long long)gm*ldc + gn] = acc[mi][ni] + bias[gn];
        }
    }
}

// ----------------------------------- host -----------------------------------
extern "C" void kernel_launch(void* const* d_in, const int* in_sizes, int n_in,
                              void* d_out, int out_size) {
    const float* x      = (const float*)d_in[0];
    const float* cond   = (const float*)d_in[1];
    const float* init_w = (const float*)d_in[2];
    const float* init_b = (const float*)d_in[3];
    const float* dc_w   = (const float*)d_in[4];
    const float* dc_b   = (const float*)d_in[5];
    const float* ln1_g  = (const float*)d_in[6];
    const float* ln1_b  = (const float*)d_in[7];
    const float* qkv_w  = (const float*)d_in[8];
    const float* qkv_b  = (const float*)d_in[9];
    const float* proj_w = (const float*)d_in[10];
    const float* proj_b = (const float*)d_in[11];
    const float* ln2_g  = (const float*)d_in[12];
    const float* ln2_b  = (const float*)d_in[13];
    const float* ff1_w  = (const float*)d_in[14];
    const float* ff1_b  = (const float*)d_in[15];
    const float* ff2_w  = (const float*)d_in[16];
    const float* ff2_b  = (const float*)d_in[17];
    const float* mag_w  = (const float*)d_in[18];
    const float* mag_b  = (const float*)d_in[19];
    const float* ph_w   = (const float*)d_in[20];
    const float* ph_b   = (const float*)d_in[21];
    float* out = (float*)d_out;

    float *tok, *t, *buf1, *bhd;
    cudaGetSymbolAddress((void**)&tok,  g_tok);
    cudaGetSymbolAddress((void**)&t,    g_t);
    cudaGetSymbolAddress((void**)&buf1, g_buf1);
    cudaGetSymbolAddress((void**)&bhd,  g_bhd);
    __half *b1h,*qh,*kh,*vth,*shh,*aoh,*hidh,*tsh,
           *wqh,*wph2,*wf1h,*wf2h,*whd;
    cudaGetSymbolAddress((void**)&b1h,  g_b1hi);
    cudaGetSymbolAddress((void**)&qh,   g_qhi);
    cudaGetSymbolAddress((void**)&kh,   g_khi);
    cudaGetSymbolAddress((void**)&vth,  g_vthi);
    cudaGetSymbolAddress((void**)&shh,  g_shi);
    cudaGetSymbolAddress((void**)&aoh,  g_aohi);
    cudaGetSymbolAddress((void**)&hidh, g_hidhi);
    cudaGetSymbolAddress((void**)&tsh,  g_tshi);
    cudaGetSymbolAddress((void**)&wqh,  g_wqkvhi);
    cudaGetSymbolAddress((void**)&wph2, g_wprhi);
    cudaGetSymbolAddress((void**)&wf1h, g_wf1hi);
    cudaGetSymbolAddress((void**)&wf2h, g_wf2hi);
    cudaGetSymbolAddress((void**)&whd,  g_whd);

    cudaFuncSetAttribute(k_mgemm<1,0,0,0,0,0,0,1,1>, cudaFuncAttributeMaxDynamicSharedMemorySize, MG_SMEM);
    cudaFuncSetAttribute(k_mgemm<0,0,0,0,1,0,2,1,0>, cudaFuncAttributeMaxDynamicSharedMemorySize, MG_SMEM);
    cudaFuncSetAttribute(k_mgemm<0,0,0,0,0,1,2,1,0>, cudaFuncAttributeMaxDynamicSharedMemorySize, MG_SMEM);
    cudaFuncSetAttribute(k_mgemm<1,0,1,0,0,0,0,1,0>, cudaFuncAttributeMaxDynamicSharedMemorySize, MG_SMEM);
    cudaFuncSetAttribute(k_mgemm<1,1,0,0,0,0,2,1,0>, cudaFuncAttributeMaxDynamicSharedMemorySize, MG_SMEM);
    cudaFuncSetAttribute(k_mgemm<1,0,1,0,0,0,2,1,0>, cudaFuncAttributeMaxDynamicSharedMemorySize, MG_SMEM);
    cudaFuncSetAttribute(k_mgemm<1,0,0,1,0,0,0,1,0>, cudaFuncAttributeMaxDynamicSharedMemorySize, MG_SMEM);

    // ---- convert all weights to single fp16; gather head biases ----
    {
        long long n;
        n = (long long)LAYERS*3*HD*HD; k_split1<<<(int)((n/4+255)/256),256>>>(qkv_w,  wqh,  n);
        n = (long long)LAYERS*HD*HD;   k_split1<<<(int)((n/4+255)/256),256>>>(proj_w, wph2, n);
        n = (long long)LAYERS*4*HD*HD; k_split1<<<(int)((n/4+255)/256),256>>>(ff1_w,  wf1h, n);
        n = (long long)LAYERS*4*HD*HD; k_split1<<<(int)((n/4+255)/256),256>>>(ff2_w,  wf2h, n);
        n = (long long)16384*512;      k_split1<<<(int)((n/4+255)/256),256>>>(mag_w,  whd,  n);
        n = (long long)16384*512;      k_split1<<<(int)((n/4+255)/256),256>>>(ph_w,   whd + 16384LL*512, n);
        cudaMemcpyAsync(bhd,         mag_b, 16384*sizeof(float), cudaMemcpyDeviceToDevice);
        cudaMemcpyAsync(bhd + 16384, ph_b,  16384*sizeof(float), cudaMemcpyDeviceToDevice);
    }

    // ---- FFT + token build + init linear + shift ----
    int nfft = BATCH*16*64*33;
    k_dft1<<<(nfft+255)/256, 256>>>(x);
    k_dft2<<<(nfft+255)/256, 256>>>();
    {
        dim3 g(1024/128, ROWS/128);
        k_gemm32<<<g,256>>>(tok, init_w, init_b, buf1, ROWS, 1024, 32, 32, 32, 1024);
    }
    k_shift<<<(ROWS*HD+255)/256, 256>>>(cond, dc_w, dc_b);

    for (int l = 0; l < LAYERS; l++) {
        const float* qb  = qkv_b + l*3*HD;
        const float* pb  = proj_b + l*HD;
        const float* f1b = ff1_b + l*4*HD;
        const float* f2b = ff2_b + l*HD;
        const __half* lwqh = wqh  + (long long)l*3*HD*HD;
        const __half* lwph = wph2 + (long long)l*HD*HD;
        const __half* lw1h = wf1h + (long long)l*4*HD*HD;
        const __half* lw2h = wf2h + (long long)l*4*HD*HD;

        k_ln<<<ROWS,256>>>(ln1_g + l*HD, ln1_b + l*HD);

        { // qkv GEMM with fused RoPE + reorganize epilogue (bit-exact fusion)
            dim3 g(3072/128, ROWS/128, 1);
            k_mgemm<1,0,0,0,0,0,0,1,1><<<g,256,MG_SMEM>>>(
                b1h, b1h, HD, lwqh, lwqh, HD, qb, nullptr,
                nullptr, nullptr, nullptr, 3*HD,
                ROWS, 3*HD, HD, 1.f, 1, 0,0,0,0,0,0);
        }

        { // S = alpha * Q K^T (causal; masked region zeroed in epilogue)
            dim3 g(17, 17, NZ);
            k_mgemm<0,0,0,0,1,0,2,1,0><<<g,256,MG_SMEM>>>(
                qh, qh, HDIM, kh, kh, HDIM, nullptr, nullptr,
                nullptr, shh, nullptr, NTOK,
                NTOK, NTOK, HDIM, 0.08838834764831845f,
                NHEADS, (long long)NHEADS*NTOK*HDIM, (long long)NTOK*HDIM,
                        (long long)NHEADS*NTOK*HDIM, (long long)NTOK*HDIM,
                        (long long)NHEADS*SZZ, SZZ);
        }
        { dim3 g(NTOK, NZ); k_softmax<<<g,256>>>(); }
        { // O = S V  (single-product, TRIK; single fp16 out)
            dim3 g(1, 17, NZ);
            k_mgemm<0,0,0,0,0,1,2,1,0><<<g,256,MG_SMEM>>>(
                shh, shh, NTOK, vth, vth, NTOK, nullptr, nullptr,
                nullptr, aoh, nullptr, HD,
                NTOK, HDIM, NTOK, 1.f,
                NHEADS, (long long)NHEADS*SZZ, SZZ,
                        (long long)NHEADS*HDIM*NTOK, (long long)HDIM*NTOK,
                        (long long)NTOK*HD, (long long)HDIM);
        }
        { // proj + residual -> t  (single-product)
            dim3 g(HD/128, ROWS/128, 1);
            k_mgemm<1,0,1,0,0,0,0,1,0><<<g,256,MG_SMEM>>>(
                aoh, aoh, HD, lwph, lwph, HD, pb, t,
                t, nullptr, nullptr, HD,
                ROWS, HD, HD, 1.f, 1, 0,0,0,0,0,0);
        }
        k_ln<<<ROWS,256>>>(ln2_g + l*HD, ln2_b + l*HD);
        { // ff1 + gelu -> hid single fp16 (single-product)
            dim3 g(4096/128, ROWS/128, 1);
            k_mgemm<1,1,0,0,0,0,2,1,0><<<g,256,MG_SMEM>>>(
                b1h, b1h, HD, lw1h, lw1h, HD, f1b, nullptr,
                nullptr, hidh, nullptr, 4*HD,
                ROWS, 4*HD, HD, 1.f, 1, 0,0,0,0,0,0);
        }
        if (l < LAYERS-1) { // ff2 + residual -> t  (single-product)
            dim3 g(HD/128, ROWS/128, 1);
            k_mgemm<1,0,1,0,0,0,0,1,0><<<g,256,MG_SMEM>>>(
                hidh, hidh, 4*HD, lw2h, lw2h, 4*HD, f2b, t,
                t, nullptr, nullptr, HD,
                ROWS, HD, 4*HD, 1.f, 1, 0,0,0,0,0,0);
        } else {            // last layer: fused fp16 convert -> tsh
            dim3 g(HD/128, ROWS/128, 1);
            k_mgemm<1,0,1,0,0,0,2,1,0><<<g,256,MG_SMEM>>>(
                hidh, hidh, 4*HD, lw2h, lw2h, 4*HD, f2b, t,
                nullptr, tsh, nullptr, HD,
                ROWS, HD, 4*HD, 1.f, 1, 0,0,0,0,0,0);
        }
    }

    // heads: single merged launch, z in {0 = mag, 1 = phase}
    const long long HEAD_ELEMS = (long long)BATCH*16*1024*NTOK;
    {
        dim3 g(16384/128, ROWS/128, 2);
        k_mgemm<1,0,0,1,0,0,0,1,0><<<g,256,MG_SMEM>>>(
            tsh, tsh, HD, whd, whd, 512, bhd, nullptr,
            out, nullptr, nullptr, 0,
            ROWS, 16384, 512, 1.f,
            1, 512, 0, 16384LL*512, 0, HEAD_ELEMS, 16384);
    }
}